// round 11
// baseline (speedup 1.0000x reference)
#include <cuda_runtime.h>
#include <math.h>
#include <stdint.h>

#define B_SZ 64
#define L_SEQ 196
#define D_MODEL 192
#define DEPTH 24
#define D_INNER 384
#define D_STATE 16
#define D_CONV 4
#define DT_RANK 12
#define N_CLS 1000
#define XPROJ_N (DT_RANK + 2*D_STATE)   // 44
#define ROWS (B_SZ*L_SEQ)               // 12544
#define K_PATCH 768                      // 3*16*16

// ---------------- scratch ----------------
__device__ float g_hidden[ROWS*D_MODEL];
__device__ float g_residual[ROWS*D_MODEL];
__device__ float g_hn[ROWS*D_MODEL];
__device__ float g_xz[ROWS*2*D_INNER];
__device__ float g_xb[ROWS*D_INNER];
__device__ float g_xdbl[ROWS*XPROJ_N];
__device__ float g_y[ROWS*D_INNER];
__device__ float g_wpatch[D_MODEL*K_PATCH];
__device__ float g_win[DEPTH*2*D_INNER*D_MODEL];
__device__ float g_wx[DEPTH*XPROJ_N*D_INNER];
__device__ float g_wout[DEPTH*D_MODEL*D_INNER];

// ================= helpers =================
__device__ __forceinline__ uint32_t f2tf32(float f) {
    uint32_t o;
    asm("cvt.rna.tf32.f32 %0, %1;" : "=r"(o) : "f"(f));
    return o;
}
__device__ __forceinline__ float tf32r(float f) { return __uint_as_float(f2tf32(f)); }

__global__ void round_tf32_kernel(const float* __restrict__ src, float* __restrict__ dst, int n) {
    int i = blockIdx.x * blockDim.x + threadIdx.x;
    int stride = gridDim.x * blockDim.x;
    for (; i < n; i += stride) dst[i] = tf32r(src[i]);
}

__device__ __forceinline__ uint32_t smem_u32(const void* p) {
    uint32_t a;
    asm("{ .reg .u64 t; cvta.to.shared.u64 t, %1; cvt.u32.u64 %0, t; }" : "=r"(a) : "l"(p));
    return a;
}
#define CP_ASYNC(dst, src, sz) \
    asm volatile("cp.async.cg.shared.global [%0], [%1], 16, %2;" :: "r"(dst), "l"(src), "r"(sz))
#define CP_COMMIT() asm volatile("cp.async.commit_group;" ::: "memory")
#define CP_WAIT(n)  asm volatile("cp.async.wait_group %0;" :: "n"(n) : "memory")

__device__ __forceinline__ void mma1688(float* c, const uint32_t* a, const uint32_t* b) {
    asm volatile(
        "mma.sync.aligned.m16n8k8.row.col.f32.tf32.tf32.f32 "
        "{%0,%1,%2,%3}, {%4,%5,%6,%7}, {%8,%9}, {%0,%1,%2,%3};"
        : "+f"(c[0]), "+f"(c[1]), "+f"(c[2]), "+f"(c[3])
        : "r"(a[0]), "r"(a[1]), "r"(a[2]), "r"(a[3]), "r"(b[0]), "r"(b[1]));
}

#define GA_STRIDE 36

// ================= gemm_wide: BM=128, BN=128, BK=32 =================
#define WIDE_STAGE ((128+128)*GA_STRIDE*4)   // 36864
#define WIDE_W_OFF (128*GA_STRIDE)

__global__ __launch_bounds__(256, 2) void gemm_wide(
        const float* __restrict__ A, const float* __restrict__ W,
        float* __restrict__ C, int M, int N, int K,
        const float* __restrict__ bias) {
    extern __shared__ float smem[];
    int tid = threadIdx.x;
    int wid = tid >> 5, lid = tid & 31;
    int wm = wid & 3, wn = wid >> 2;          // 4 x 2; warp tile 32 x 64
    int group = lid >> 2, tq = lid & 3;
    int bm = blockIdx.y * 128, bn = blockIdx.x * 128;
    uint32_t sb = smem_u32(smem);
    int nk = K >> 5;

    auto load_stage = [&](int st, int kc) {
        uint32_t base = sb + st * WIDE_STAGE;
        #pragma unroll
        for (int i = 0; i < 4; i++) {          // A: 128 rows x 8 quads
            int q = tid * 4 + i;
            int row = q >> 3, quad = q & 7;
            uint32_t dst = base + (row * GA_STRIDE + quad * 4) * 4;
            const float* src = A + (size_t)(bm + row) * K + (size_t)kc * 32 + quad * 4;
            CP_ASYNC(dst, src, 16);
        }
        #pragma unroll
        for (int i = 0; i < 4; i++) {          // W: 128 rows x 8 quads
            int q = tid * 4 + i;
            int row = q >> 3, quad = q & 7;
            int n = bn + row;
            uint32_t dst = base + (WIDE_W_OFF + row * GA_STRIDE + quad * 4) * 4;
            const float* src = (n < N) ? (W + (size_t)n * K + (size_t)kc * 32 + quad * 4) : W;
            CP_ASYNC(dst, src, (n < N) ? 16 : 0);
        }
        CP_COMMIT();
    };

    float acc[2][8][4] = {};
    load_stage(0, 0);
    for (int k0 = 0; k0 < nk; k0++) {
        if (k0 + 1 < nk) { load_stage((k0 + 1) & 1, k0 + 1); CP_WAIT(1); }
        else             { CP_WAIT(0); }
        __syncthreads();
        const float* sA = smem + (size_t)(k0 & 1) * (WIDE_STAGE / 4);
        const float* sW = sA + WIDE_W_OFF;
        #pragma unroll
        for (int kk = 0; kk < 32; kk += 8) {
            uint32_t a[2][4], b[8][2];
            #pragma unroll
            for (int mi = 0; mi < 2; mi++) {
                int r = wm * 32 + mi * 16 + group;
                a[mi][0] = __float_as_uint(sA[r * GA_STRIDE + kk + tq]);
                a[mi][1] = __float_as_uint(sA[(r + 8) * GA_STRIDE + kk + tq]);
                a[mi][2] = __float_as_uint(sA[r * GA_STRIDE + kk + tq + 4]);
                a[mi][3] = __float_as_uint(sA[(r + 8) * GA_STRIDE + kk + tq + 4]);
            }
            #pragma unroll
            for (int ni = 0; ni < 8; ni++) {
                int r = wn * 64 + ni * 8 + group;
                b[ni][0] = __float_as_uint(sW[r * GA_STRIDE + kk + tq]);
                b[ni][1] = __float_as_uint(sW[r * GA_STRIDE + kk + tq + 4]);
            }
            #pragma unroll
            for (int mi = 0; mi < 2; mi++)
                #pragma unroll
                for (int ni = 0; ni < 8; ni++)
                    mma1688(acc[mi][ni], a[mi], b[ni]);
        }
        __syncthreads();
    }
    #pragma unroll
    for (int mi = 0; mi < 2; mi++) {
        int m0 = bm + wm * 32 + mi * 16 + group;
        #pragma unroll
        for (int ni = 0; ni < 8; ni++) {
            int n0 = bn + wn * 64 + ni * 8 + tq * 2;
            if (n0 < N) {
                float bx = 0.f, by = 0.f;
                if (bias) { bx = bias[n0]; by = bias[n0 + 1]; }
                *(float2*)&C[(size_t)m0 * N + n0] =
                    make_float2(acc[mi][ni][0] + bx, acc[mi][ni][1] + by);
                *(float2*)&C[(size_t)(m0 + 8) * N + n0] =
                    make_float2(acc[mi][ni][2] + bx, acc[mi][ni][3] + by);
            }
        }
    }
}

// ================= gemm_x: BM=64, BN=64, BK=32 (x_proj, N=44) =================
#define X_STAGE ((64+64)*GA_STRIDE*4)        // 18432
#define X_W_OFF (64*GA_STRIDE)

__global__ __launch_bounds__(256, 4) void gemm_x(
        const float* __restrict__ A, const float* __restrict__ W,
        float* __restrict__ C, int M, int N, int K) {
    extern __shared__ float smem[];
    int tid = threadIdx.x;
    int wid = tid >> 5, lid = tid & 31;
    int wm = wid & 1, wn = wid >> 1;          // 2 x 4; warp tile 32 x 16
    int group = lid >> 2, tq = lid & 3;
    int bm = blockIdx.x * 64;
    uint32_t sb = smem_u32(smem);
    int nk = K >> 5;

    auto load_stage = [&](int st, int kc) {
        uint32_t base = sb + st * X_STAGE;
        #pragma unroll
        for (int i = 0; i < 2; i++) {          // A: 64 rows x 8 quads = 512
            int q = tid * 2 + i;
            int row = q >> 3, quad = q & 7;
            uint32_t dst = base + (row * GA_STRIDE + quad * 4) * 4;
            const float* src = A + (size_t)(bm + row) * K + (size_t)kc * 32 + quad * 4;
            CP_ASYNC(dst, src, 16);
        }
        #pragma unroll
        for (int i = 0; i < 2; i++) {          // W: 64 rows x 8 quads = 512
            int q = tid * 2 + i;
            int row = q >> 3, quad = q & 7;
            uint32_t dst = base + (X_W_OFF + row * GA_STRIDE + quad * 4) * 4;
            const float* src = (row < N) ? (W + (size_t)row * K + (size_t)kc * 32 + quad * 4) : W;
            CP_ASYNC(dst, src, (row < N) ? 16 : 0);
        }
        CP_COMMIT();
    };

    float acc[2][2][4] = {};
    load_stage(0, 0);
    for (int k0 = 0; k0 < nk; k0++) {
        if (k0 + 1 < nk) { load_stage((k0 + 1) & 1, k0 + 1); CP_WAIT(1); }
        else             { CP_WAIT(0); }
        __syncthreads();
        const float* sA = smem + (size_t)(k0 & 1) * (X_STAGE / 4);
        const float* sW = sA + X_W_OFF;
        #pragma unroll
        for (int kk = 0; kk < 32; kk += 8) {
            uint32_t a[2][4], b[2][2];
            #pragma unroll
            for (int mi = 0; mi < 2; mi++) {
                int r = wm * 32 + mi * 16 + group;
                a[mi][0] = __float_as_uint(sA[r * GA_STRIDE + kk + tq]);
                a[mi][1] = __float_as_uint(sA[(r + 8) * GA_STRIDE + kk + tq]);
                a[mi][2] = __float_as_uint(sA[r * GA_STRIDE + kk + tq + 4]);
                a[mi][3] = __float_as_uint(sA[(r + 8) * GA_STRIDE + kk + tq + 4]);
            }
            #pragma unroll
            for (int ni = 0; ni < 2; ni++) {
                int r = wn * 16 + ni * 8 + group;
                b[ni][0] = __float_as_uint(sW[r * GA_STRIDE + kk + tq]);
                b[ni][1] = __float_as_uint(sW[r * GA_STRIDE + kk + tq + 4]);
            }
            #pragma unroll
            for (int mi = 0; mi < 2; mi++)
                #pragma unroll
                for (int ni = 0; ni < 2; ni++)
                    mma1688(acc[mi][ni], a[mi], b[ni]);
        }
        __syncthreads();
    }
    #pragma unroll
    for (int mi = 0; mi < 2; mi++) {
        int m0 = bm + wm * 32 + mi * 16 + group;
        #pragma unroll
        for (int ni = 0; ni < 2; ni++) {
            int n0 = wn * 16 + ni * 8 + tq * 2;
            if (n0 < N) {
                *(float2*)&C[(size_t)m0 * N + n0] = make_float2(acc[mi][ni][0], acc[mi][ni][1]);
                *(float2*)&C[(size_t)(m0 + 8) * N + n0] = make_float2(acc[mi][ni][2], acc[mi][ni][3]);
            }
        }
    }
}

// ================= im2col =================
__global__ void im2col_kernel(const float* __restrict__ x, float* __restrict__ col) {
    int idx = blockIdx.x * blockDim.x + threadIdx.x;
    if (idx >= ROWS * K_PATCH) return;
    int k  = idx % K_PATCH;
    int bl = idx / K_PATCH;
    int l  = bl % L_SEQ;
    int b  = bl / L_SEQ;
    int c  = k / 256;
    int rem = k % 256;
    int i = rem / 16, j = rem % 16;
    int ph = l / 14, pw = l % 14;
    col[idx] = tf32r(x[((b*3 + c)*224 + ph*16 + i)*224 + pw*16 + j]);
}

// ================= fused residual add + LayerNorm =================
__global__ void add_ln_kernel(const float* __restrict__ hidden, float* __restrict__ residual,
                              float* __restrict__ hn, const float* __restrict__ w,
                              const float* __restrict__ b, int first) {
    int row = blockIdx.x;
    int t = threadIdx.x;               // 192 threads
    int idx = row*D_MODEL + t;
    float h = hidden[idx];
    float r = first ? h : (residual[idx] + h);
    residual[idx] = r;
    __shared__ float red[6];
    float s = r;
    #pragma unroll
    for (int o = 16; o > 0; o >>= 1) s += __shfl_xor_sync(0xffffffffu, s, o);
    if ((t & 31) == 0) red[t >> 5] = s;
    __syncthreads();
    float mean = (red[0]+red[1]+red[2]+red[3]+red[4]+red[5]) * (1.f/192.f);
    __syncthreads();
    float dv = r - mean;
    s = dv*dv;
    #pragma unroll
    for (int o = 16; o > 0; o >>= 1) s += __shfl_xor_sync(0xffffffffu, s, o);
    if ((t & 31) == 0) red[t >> 5] = s;
    __syncthreads();
    float var = (red[0]+red[1]+red[2]+red[3]+red[4]+red[5]) * (1.f/192.f);
    hn[idx] = tf32r(dv * rsqrtf(var + 1e-5f) * w[t] + b[t]);
}

// ================= causal depthwise conv1d + SiLU, sliding window =================
__global__ __launch_bounds__(384) void conv_silu_kernel(
        const float* __restrict__ xz, const float* __restrict__ cw,
        const float* __restrict__ cb, float* __restrict__ xb) {
    int d = threadIdx.x;
    int b = blockIdx.x;
    int l0 = blockIdx.y * 49;
    float w0 = cw[d*D_CONV+0], w1 = cw[d*D_CONV+1], w2 = cw[d*D_CONV+2], w3 = cw[d*D_CONV+3];
    float bias = cb[d];
    size_t base = (size_t)b*L_SEQ*(2*D_INNER) + d;
    size_t obase = (size_t)b*L_SEQ*D_INNER + d;
    float xm3 = (l0 >= 3) ? xz[base + (size_t)(l0-3)*(2*D_INNER)] : 0.f;
    float xm2 = (l0 >= 2) ? xz[base + (size_t)(l0-2)*(2*D_INNER)] : 0.f;
    float xm1 = (l0 >= 1) ? xz[base + (size_t)(l0-1)*(2*D_INNER)] : 0.f;
    #pragma unroll 7
    for (int l = l0; l < l0 + 49; l++) {
        float x0 = xz[base + (size_t)l*(2*D_INNER)];
        float acc = bias + w0*xm3 + w1*xm2 + w2*xm1 + w3*x0;
        float sig = 1.f / (1.f + __expf(-acc));
        xb[obase + (size_t)l*D_INNER] = acc * sig;
        xm3 = xm2; xm2 = xm1; xm1 = x0;
    }
}

// ================= scan =================
__global__ __launch_bounds__(128) void scan_kernel(
        const float* __restrict__ xb, const float* __restrict__ xdbl,
        const float* __restrict__ xz, const float* __restrict__ A_log,
        const float* __restrict__ Dskip, const float* __restrict__ dtw,
        const float* __restrict__ dtb, float* __restrict__ y) {
    int b = blockIdx.y;
    int d = blockIdx.x * 128 + threadIdx.x;
    __shared__ float sdbl[L_SEQ][XPROJ_N];
    const float* src = &xdbl[(size_t)b*L_SEQ*XPROJ_N];
    for (int idx = threadIdx.x; idx < L_SEQ*XPROJ_N; idx += 128)
        ((float*)sdbl)[idx] = src[idx];
    __syncthreads();

    float wdt[DT_RANK];
    #pragma unroll
    for (int r = 0; r < DT_RANK; r++) wdt[r] = dtw[d*DT_RANK + r];
    float bdt = dtb[d];
    float a[D_STATE], h[D_STATE];
    #pragma unroll
    for (int n = 0; n < D_STATE; n++) {
        a[n] = -__expf(A_log[d*D_STATE + n]);
        h[n] = 0.f;
    }
    bool structured = true;
    #pragma unroll
    for (int n = 0; n < D_STATE; n++)
        structured = structured && (a[n] == a[0]*(float)(n+1));
    float Dd = Dskip[d];

    size_t base0 = (size_t)b*L_SEQ*D_INNER + d;
    size_t zbase0 = (size_t)b*L_SEQ*(2*D_INNER) + D_INNER + d;
    float u_cur = xb[base0];
    float z_cur = xz[zbase0];
    for (int l = 0; l < L_SEQ; l++) {
        float u = u_cur, z = z_cur;
        if (l + 1 < L_SEQ) {
            u_cur = xb[base0 + (size_t)(l+1)*D_INNER];
            z_cur = xz[zbase0 + (size_t)(l+1)*(2*D_INNER)];
        }
        float dt = bdt;
        #pragma unroll
        for (int r = 0; r < DT_RANK; r++) dt += sdbl[l][r] * wdt[r];
        dt = (dt > 15.f) ? dt : __logf(1.f + __expf(dt));
        float du = dt * u;
        float e[D_STATE];
        if (structured) {
            float w = __expf(dt * a[0]);
            e[0] = w;
            float w2 = w * w;
            e[1] = w2;
            float w4 = w2 * w2;
            e[2] = w2 * w;  e[3] = w4;
            e[4] = w4 * w;  e[5] = w4 * w2;  e[6] = w4 * e[2]; e[7] = w4 * w4;
            #pragma unroll
            for (int n = 8; n < D_STATE; n++) e[n] = e[7] * e[n - 8];
        } else {
            #pragma unroll
            for (int n = 0; n < D_STATE; n++) e[n] = __expf(dt * a[n]);
        }
        float yv = 0.f;
        #pragma unroll
        for (int n = 0; n < D_STATE; n++) {
            h[n] = e[n] * h[n] + du * sdbl[l][DT_RANK + n];
            yv  += h[n] * sdbl[l][DT_RANK + D_STATE + n];
        }
        yv += u * Dd;
        float sig = 1.f / (1.f + __expf(-z));
        y[base0 + (size_t)l*D_INNER] = tf32r(yv * (z * sig));
    }
}

// ================= final =================
__global__ void final_kernel(const float* __restrict__ residual, const float* __restrict__ hidden,
                             const float* __restrict__ nw, const float* __restrict__ nb,
                             const float* __restrict__ hw, const float* __restrict__ hb,
                             float* __restrict__ out) {
    int b = blockIdx.x;
    int t = threadIdx.x;               // 256 threads
    __shared__ float sh[D_MODEL];
    __shared__ float red[8];
    int row = b*L_SEQ + (L_SEQ - 1);
    float v = 0.f;
    if (t < D_MODEL) v = residual[row*D_MODEL + t] + hidden[row*D_MODEL + t];
    float s = v;
    #pragma unroll
    for (int o = 16; o > 0; o >>= 1) s += __shfl_xor_sync(0xffffffffu, s, o);
    if ((t & 31) == 0) red[t >> 5] = s;
    __syncthreads();
    float mean = 0.f;
    #pragma unroll
    for (int i = 0; i < 8; i++) mean += red[i];
    mean *= (1.f/192.f);
    __syncthreads();
    float dv = (t < D_MODEL) ? (v - mean) : 0.f;
    s = dv*dv;
    #pragma unroll
    for (int o = 16; o > 0; o >>= 1) s += __shfl_xor_sync(0xffffffffu, s, o);
    if ((t & 31) == 0) red[t >> 5] = s;
    __syncthreads();
    float var = 0.f;
    #pragma unroll
    for (int i = 0; i < 8; i++) var += red[i];
    var *= (1.f/192.f);
    if (t < D_MODEL) sh[t] = dv * rsqrtf(var + 1e-5f) * nw[t] + nb[t];
    __syncthreads();
    for (int o = t; o < N_CLS; o += 256) {
        float acc = hb[o];
        #pragma unroll 4
        for (int k = 0; k < D_MODEL; k++) acc += sh[k] * hw[o*D_MODEL + k];
        out[b*N_CLS + o] = acc;
    }
}

extern "C" void kernel_launch(void* const* d_in, const int* in_sizes, int n_in,
                              void* d_out, int out_size) {
    const float* x        = (const float*)d_in[0];
    const float* patch_w  = (const float*)d_in[1];
    const float* patch_b  = (const float*)d_in[2];
    const float* in_w     = (const float*)d_in[3];
    const float* conv_w   = (const float*)d_in[4];
    const float* conv_b   = (const float*)d_in[5];
    const float* xproj_w  = (const float*)d_in[6];
    const float* dt_w     = (const float*)d_in[7];
    const float* dt_b     = (const float*)d_in[8];
    const float* A_log    = (const float*)d_in[9];
    const float* D_skip   = (const float*)d_in[10];
    const float* out_w    = (const float*)d_in[11];
    const float* norm_w   = (const float*)d_in[12];
    const float* norm_b   = (const float*)d_in[13];
    const float* normf_w  = (const float*)d_in[14];
    const float* normf_b  = (const float*)d_in[15];
    const float* head_w   = (const float*)d_in[16];
    const float* head_b   = (const float*)d_in[17];
    float* out = (float*)d_out;

    float *hidden, *residual, *hn, *xz, *xb, *xdbl, *y;
    float *wpatch, *win, *wx, *wout;
    cudaGetSymbolAddress((void**)&hidden,   g_hidden);
    cudaGetSymbolAddress((void**)&residual, g_residual);
    cudaGetSymbolAddress((void**)&hn,       g_hn);
    cudaGetSymbolAddress((void**)&xz,       g_xz);
    cudaGetSymbolAddress((void**)&xb,       g_xb);
    cudaGetSymbolAddress((void**)&xdbl,     g_xdbl);
    cudaGetSymbolAddress((void**)&y,        g_y);
    cudaGetSymbolAddress((void**)&wpatch,   g_wpatch);
    cudaGetSymbolAddress((void**)&win,      g_win);
    cudaGetSymbolAddress((void**)&wx,       g_wx);
    cudaGetSymbolAddress((void**)&wout,     g_wout);

    cudaFuncSetAttribute(gemm_wide, cudaFuncAttributeMaxDynamicSharedMemorySize, 2*WIDE_STAGE);
    cudaFuncSetAttribute(gemm_x,    cudaFuncAttributeMaxDynamicSharedMemorySize, 2*X_STAGE);
    cudaFuncSetAttribute(gemm_wide, cudaFuncAttributePreferredSharedMemoryCarveout, 100);
    cudaFuncSetAttribute(gemm_x,    cudaFuncAttributePreferredSharedMemoryCarveout, 100);

    // pre-round GEMM weights to tf32
    round_tf32_kernel<<<512, 256>>>(patch_w, wpatch, D_MODEL*K_PATCH);
    round_tf32_kernel<<<2048, 256>>>(in_w,   win,    DEPTH*2*D_INNER*D_MODEL);
    round_tf32_kernel<<<512, 256>>>(xproj_w, wx,     DEPTH*XPROJ_N*D_INNER);
    round_tf32_kernel<<<1024, 256>>>(out_w,  wout,   DEPTH*D_MODEL*D_INNER);

    // patch embed
    im2col_kernel<<<(ROWS*K_PATCH + 255)/256, 256>>>(x, xz);
    gemm_wide<<<dim3(2, ROWS/128), 256, 2*WIDE_STAGE>>>(xz, wpatch, hidden,
                                                        ROWS, D_MODEL, K_PATCH, patch_b);

    for (int i = 0; i < DEPTH; i++) {
        add_ln_kernel<<<ROWS, D_MODEL>>>(hidden, residual, hn,
                                         norm_w + (size_t)i*D_MODEL, norm_b + (size_t)i*D_MODEL, i == 0);
        gemm_wide<<<dim3(6, ROWS/128), 256, 2*WIDE_STAGE>>>(
            hn, win + (size_t)i*2*D_INNER*D_MODEL, xz, ROWS, 2*D_INNER, D_MODEL, nullptr);
        conv_silu_kernel<<<dim3(B_SZ, 4), 384>>>(xz, conv_w + (size_t)i*D_INNER*D_CONV,
                                                 conv_b + (size_t)i*D_INNER, xb);
        gemm_x<<<ROWS/64, 256, 2*X_STAGE>>>(
            xb, wx + (size_t)i*XPROJ_N*D_INNER, xdbl, ROWS, XPROJ_N, D_INNER);
        scan_kernel<<<dim3(D_INNER/128, B_SZ), 128>>>(
            xb, xdbl, xz, A_log + (size_t)i*D_INNER*D_STATE, D_skip + (size_t)i*D_INNER,
            dt_w + (size_t)i*D_INNER*DT_RANK, dt_b + (size_t)i*D_INNER, y);
        gemm_wide<<<dim3(2, ROWS/128), 256, 2*WIDE_STAGE>>>(
            y, wout + (size_t)i*D_MODEL*D_INNER, hidden, ROWS, D_MODEL, D_INNER, nullptr);
    }

    final_kernel<<<B_SZ, 256>>>(residual, hidden, normf_w, normf_b, head_w, head_b, out);
}

// round 12
// speedup vs baseline: 1.0424x; 1.0424x over previous
#include <cuda_runtime.h>
#include <math.h>
#include <stdint.h>

#define B_SZ 64
#define L_SEQ 196
#define D_MODEL 192
#define DEPTH 24
#define D_INNER 384
#define D_STATE 16
#define D_CONV 4
#define DT_RANK 12
#define N_CLS 1000
#define XPROJ_N (DT_RANK + 2*D_STATE)   // 44
#define ROWS (B_SZ*L_SEQ)               // 12544
#define K_PATCH 768                      // 3*16*16

// ---------------- scratch ----------------
__device__ float g_hidden[ROWS*D_MODEL];
__device__ float g_residual[ROWS*D_MODEL];
__device__ float g_hn[ROWS*D_MODEL];
__device__ float g_xz[ROWS*2*D_INNER];
__device__ float g_xb[ROWS*D_INNER];
__device__ float g_xdbl[ROWS*XPROJ_N];
__device__ float g_y[ROWS*D_INNER];
__device__ float g_wpatch[D_MODEL*K_PATCH];
__device__ float g_win[DEPTH*2*D_INNER*D_MODEL];
__device__ float g_wx[DEPTH*XPROJ_N*D_INNER];
__device__ float g_wout[DEPTH*D_MODEL*D_INNER];

// ================= helpers =================
__device__ __forceinline__ uint32_t f2tf32(float f) {
    uint32_t o;
    asm("cvt.rna.tf32.f32 %0, %1;" : "=r"(o) : "f"(f));
    return o;
}
__device__ __forceinline__ float tf32r(float f) { return __uint_as_float(f2tf32(f)); }

__global__ void round_tf32_kernel(const float* __restrict__ src, float* __restrict__ dst, int n) {
    int i = blockIdx.x * blockDim.x + threadIdx.x;
    int stride = gridDim.x * blockDim.x;
    for (; i < n; i += stride) dst[i] = tf32r(src[i]);
}

__device__ __forceinline__ uint32_t smem_u32(const void* p) {
    uint32_t a;
    asm("{ .reg .u64 t; cvta.to.shared.u64 t, %1; cvt.u32.u64 %0, t; }" : "=r"(a) : "l"(p));
    return a;
}
#define CP_ASYNC(dst, src, sz) \
    asm volatile("cp.async.cg.shared.global [%0], [%1], 16, %2;" :: "r"(dst), "l"(src), "r"(sz))
#define CP_COMMIT() asm volatile("cp.async.commit_group;" ::: "memory")
#define CP_WAIT(n)  asm volatile("cp.async.wait_group %0;" :: "n"(n) : "memory")

__device__ __forceinline__ void mma1688(float* c, const uint32_t* a, const uint32_t* b) {
    asm volatile(
        "mma.sync.aligned.m16n8k8.row.col.f32.tf32.tf32.f32 "
        "{%0,%1,%2,%3}, {%4,%5,%6,%7}, {%8,%9}, {%0,%1,%2,%3};"
        : "+f"(c[0]), "+f"(c[1]), "+f"(c[2]), "+f"(c[3])
        : "r"(a[0]), "r"(a[1]), "r"(a[2]), "r"(a[3]), "r"(b[0]), "r"(b[1]));
}

#define GA_STRIDE 36

// ================= gemm_mma: BM=128, BN=64, BK=32 (out_proj/patch, N%64 handled) =================
#define STAGE_BYTES ((128+64)*GA_STRIDE*4)   // 27648
#define SMEM_W_OFF (128*GA_STRIDE)

__global__ __launch_bounds__(256, 3) void gemm_mma(
        const float* __restrict__ A, const float* __restrict__ W,
        float* __restrict__ C, int M, int N, int K,
        const float* __restrict__ bias) {
    extern __shared__ float smem[];
    int tid = threadIdx.x;
    int wid = tid >> 5, lid = tid & 31;
    int wm = wid & 3, wn = wid >> 2;
    int group = lid >> 2, tq = lid & 3;
    int bm = blockIdx.y * 128, bn = blockIdx.x * 64;
    uint32_t sb = smem_u32(smem);
    int nk = K >> 5;

    auto load_stage = [&](int st, int kc) {
        uint32_t base = sb + st * STAGE_BYTES;
        #pragma unroll
        for (int i = 0; i < 4; i++) {
            int q = tid * 4 + i;
            int row = q >> 3, quad = q & 7;
            uint32_t dst = base + (row * GA_STRIDE + quad * 4) * 4;
            const float* src = A + (size_t)(bm + row) * K + (size_t)kc * 32 + quad * 4;
            CP_ASYNC(dst, src, 16);
        }
        #pragma unroll
        for (int i = 0; i < 2; i++) {
            int q = tid * 2 + i;
            int row = q >> 3, quad = q & 7;
            int n = bn + row;
            uint32_t dst = base + (SMEM_W_OFF + row * GA_STRIDE + quad * 4) * 4;
            const float* src = (n < N) ? (W + (size_t)n * K + (size_t)kc * 32 + quad * 4) : W;
            CP_ASYNC(dst, src, (n < N) ? 16 : 0);
        }
        CP_COMMIT();
    };

    float acc[2][4][4] = {};
    load_stage(0, 0);
    for (int k0 = 0; k0 < nk; k0++) {
        if (k0 + 1 < nk) { load_stage((k0 + 1) & 1, k0 + 1); CP_WAIT(1); }
        else             { CP_WAIT(0); }
        __syncthreads();
        const float* sA = smem + (size_t)(k0 & 1) * (STAGE_BYTES / 4);
        const float* sW = sA + SMEM_W_OFF;
        #pragma unroll
        for (int kk = 0; kk < 32; kk += 8) {
            uint32_t a[2][4], b[4][2];
            #pragma unroll
            for (int mi = 0; mi < 2; mi++) {
                int r = wm * 32 + mi * 16 + group;
                a[mi][0] = __float_as_uint(sA[r * GA_STRIDE + kk + tq]);
                a[mi][1] = __float_as_uint(sA[(r + 8) * GA_STRIDE + kk + tq]);
                a[mi][2] = __float_as_uint(sA[r * GA_STRIDE + kk + tq + 4]);
                a[mi][3] = __float_as_uint(sA[(r + 8) * GA_STRIDE + kk + tq + 4]);
            }
            #pragma unroll
            for (int ni = 0; ni < 4; ni++) {
                int r = wn * 32 + ni * 8 + group;
                b[ni][0] = __float_as_uint(sW[r * GA_STRIDE + kk + tq]);
                b[ni][1] = __float_as_uint(sW[r * GA_STRIDE + kk + tq + 4]);
            }
            #pragma unroll
            for (int mi = 0; mi < 2; mi++)
                #pragma unroll
                for (int ni = 0; ni < 4; ni++)
                    mma1688(acc[mi][ni], a[mi], b[ni]);
        }
        __syncthreads();
    }
    #pragma unroll
    for (int mi = 0; mi < 2; mi++) {
        int m0 = bm + wm * 32 + mi * 16 + group;
        #pragma unroll
        for (int ni = 0; ni < 4; ni++) {
            int n0 = bn + wn * 32 + ni * 8 + tq * 2;
            if (n0 < N) {
                float bx = 0.f, by = 0.f;
                if (bias) { bx = bias[n0]; by = bias[n0 + 1]; }
                float2 o0 = make_float2(acc[mi][ni][0] + bx, acc[mi][ni][1] + by);
                float2 o1 = make_float2(acc[mi][ni][2] + bx, acc[mi][ni][3] + by);
                *(float2*)&C[(size_t)m0 * N + n0] = o0;
                *(float2*)&C[(size_t)(m0 + 8) * N + n0] = o1;
            }
        }
    }
}

// ================= gemm_wide: BM=128, BN=128, BK=32 (in_proj, N=768) =================
#define WIDE_STAGE ((128+128)*GA_STRIDE*4)   // 36864
#define WIDE_W_OFF (128*GA_STRIDE)

__global__ __launch_bounds__(256, 2) void gemm_wide(
        const float* __restrict__ A, const float* __restrict__ W,
        float* __restrict__ C, int M, int N, int K) {
    extern __shared__ float smem[];
    int tid = threadIdx.x;
    int wid = tid >> 5, lid = tid & 31;
    int wm = wid & 3, wn = wid >> 2;          // 4 x 2; warp tile 32 x 64
    int group = lid >> 2, tq = lid & 3;
    int bm = blockIdx.y * 128, bn = blockIdx.x * 128;
    uint32_t sb = smem_u32(smem);
    int nk = K >> 5;

    auto load_stage = [&](int st, int kc) {
        uint32_t base = sb + st * WIDE_STAGE;
        #pragma unroll
        for (int i = 0; i < 4; i++) {
            int q = tid * 4 + i;
            int row = q >> 3, quad = q & 7;
            uint32_t dst = base + (row * GA_STRIDE + quad * 4) * 4;
            const float* src = A + (size_t)(bm + row) * K + (size_t)kc * 32 + quad * 4;
            CP_ASYNC(dst, src, 16);
        }
        #pragma unroll
        for (int i = 0; i < 4; i++) {
            int q = tid * 4 + i;
            int row = q >> 3, quad = q & 7;
            int n = bn + row;
            uint32_t dst = base + (WIDE_W_OFF + row * GA_STRIDE + quad * 4) * 4;
            const float* src = (n < N) ? (W + (size_t)n * K + (size_t)kc * 32 + quad * 4) : W;
            CP_ASYNC(dst, src, (n < N) ? 16 : 0);
        }
        CP_COMMIT();
    };

    float acc[2][8][4] = {};
    load_stage(0, 0);
    for (int k0 = 0; k0 < nk; k0++) {
        if (k0 + 1 < nk) { load_stage((k0 + 1) & 1, k0 + 1); CP_WAIT(1); }
        else             { CP_WAIT(0); }
        __syncthreads();
        const float* sA = smem + (size_t)(k0 & 1) * (WIDE_STAGE / 4);
        const float* sW = sA + WIDE_W_OFF;
        #pragma unroll
        for (int kk = 0; kk < 32; kk += 8) {
            uint32_t a[2][4], b[8][2];
            #pragma unroll
            for (int mi = 0; mi < 2; mi++) {
                int r = wm * 32 + mi * 16 + group;
                a[mi][0] = __float_as_uint(sA[r * GA_STRIDE + kk + tq]);
                a[mi][1] = __float_as_uint(sA[(r + 8) * GA_STRIDE + kk + tq]);
                a[mi][2] = __float_as_uint(sA[r * GA_STRIDE + kk + tq + 4]);
                a[mi][3] = __float_as_uint(sA[(r + 8) * GA_STRIDE + kk + tq + 4]);
            }
            #pragma unroll
            for (int ni = 0; ni < 8; ni++) {
                int r = wn * 64 + ni * 8 + group;
                b[ni][0] = __float_as_uint(sW[r * GA_STRIDE + kk + tq]);
                b[ni][1] = __float_as_uint(sW[r * GA_STRIDE + kk + tq + 4]);
            }
            #pragma unroll
            for (int mi = 0; mi < 2; mi++)
                #pragma unroll
                for (int ni = 0; ni < 8; ni++)
                    mma1688(acc[mi][ni], a[mi], b[ni]);
        }
        __syncthreads();
    }
    #pragma unroll
    for (int mi = 0; mi < 2; mi++) {
        int m0 = bm + wm * 32 + mi * 16 + group;
        #pragma unroll
        for (int ni = 0; ni < 8; ni++) {
            int n0 = bn + wn * 64 + ni * 8 + tq * 2;
            if (n0 < N) {
                *(float2*)&C[(size_t)m0 * N + n0] = make_float2(acc[mi][ni][0], acc[mi][ni][1]);
                *(float2*)&C[(size_t)(m0 + 8) * N + n0] = make_float2(acc[mi][ni][2], acc[mi][ni][3]);
            }
        }
    }
}

// ================= gemm_x: BM=64, BN=64, BK=32 (x_proj, N=44) =================
#define X_STAGE ((64+64)*GA_STRIDE*4)        // 18432
#define X_W_OFF (64*GA_STRIDE)

__global__ __launch_bounds__(256, 4) void gemm_x(
        const float* __restrict__ A, const float* __restrict__ W,
        float* __restrict__ C, int M, int N, int K) {
    extern __shared__ float smem[];
    int tid = threadIdx.x;
    int wid = tid >> 5, lid = tid & 31;
    int wm = wid & 1, wn = wid >> 1;          // 2 x 4; warp tile 32 x 16
    int group = lid >> 2, tq = lid & 3;
    int bm = blockIdx.x * 64;
    uint32_t sb = smem_u32(smem);
    int nk = K >> 5;

    auto load_stage = [&](int st, int kc) {
        uint32_t base = sb + st * X_STAGE;
        #pragma unroll
        for (int i = 0; i < 2; i++) {
            int q = tid * 2 + i;
            int row = q >> 3, quad = q & 7;
            uint32_t dst = base + (row * GA_STRIDE + quad * 4) * 4;
            const float* src = A + (size_t)(bm + row) * K + (size_t)kc * 32 + quad * 4;
            CP_ASYNC(dst, src, 16);
        }
        #pragma unroll
        for (int i = 0; i < 2; i++) {
            int q = tid * 2 + i;
            int row = q >> 3, quad = q & 7;
            uint32_t dst = base + (X_W_OFF + row * GA_STRIDE + quad * 4) * 4;
            const float* src = (row < N) ? (W + (size_t)row * K + (size_t)kc * 32 + quad * 4) : W;
            CP_ASYNC(dst, src, (row < N) ? 16 : 0);
        }
        CP_COMMIT();
    };

    float acc[2][2][4] = {};
    load_stage(0, 0);
    for (int k0 = 0; k0 < nk; k0++) {
        if (k0 + 1 < nk) { load_stage((k0 + 1) & 1, k0 + 1); CP_WAIT(1); }
        else             { CP_WAIT(0); }
        __syncthreads();
        const float* sA = smem + (size_t)(k0 & 1) * (X_STAGE / 4);
        const float* sW = sA + X_W_OFF;
        #pragma unroll
        for (int kk = 0; kk < 32; kk += 8) {
            uint32_t a[2][4], b[2][2];
            #pragma unroll
            for (int mi = 0; mi < 2; mi++) {
                int r = wm * 32 + mi * 16 + group;
                a[mi][0] = __float_as_uint(sA[r * GA_STRIDE + kk + tq]);
                a[mi][1] = __float_as_uint(sA[(r + 8) * GA_STRIDE + kk + tq]);
                a[mi][2] = __float_as_uint(sA[r * GA_STRIDE + kk + tq + 4]);
                a[mi][3] = __float_as_uint(sA[(r + 8) * GA_STRIDE + kk + tq + 4]);
            }
            #pragma unroll
            for (int ni = 0; ni < 2; ni++) {
                int r = wn * 16 + ni * 8 + group;
                b[ni][0] = __float_as_uint(sW[r * GA_STRIDE + kk + tq]);
                b[ni][1] = __float_as_uint(sW[r * GA_STRIDE + kk + tq + 4]);
            }
            #pragma unroll
            for (int mi = 0; mi < 2; mi++)
                #pragma unroll
                for (int ni = 0; ni < 2; ni++)
                    mma1688(acc[mi][ni], a[mi], b[ni]);
        }
        __syncthreads();
    }
    #pragma unroll
    for (int mi = 0; mi < 2; mi++) {
        int m0 = bm + wm * 32 + mi * 16 + group;
        #pragma unroll
        for (int ni = 0; ni < 2; ni++) {
            int n0 = wn * 16 + ni * 8 + tq * 2;
            if (n0 < N) {
                *(float2*)&C[(size_t)m0 * N + n0] = make_float2(acc[mi][ni][0], acc[mi][ni][1]);
                *(float2*)&C[(size_t)(m0 + 8) * N + n0] = make_float2(acc[mi][ni][2], acc[mi][ni][3]);
            }
        }
    }
}

// ================= im2col =================
__global__ void im2col_kernel(const float* __restrict__ x, float* __restrict__ col) {
    int idx = blockIdx.x * blockDim.x + threadIdx.x;
    if (idx >= ROWS * K_PATCH) return;
    int k  = idx % K_PATCH;
    int bl = idx / K_PATCH;
    int l  = bl % L_SEQ;
    int b  = bl / L_SEQ;
    int c  = k / 256;
    int rem = k % 256;
    int i = rem / 16, j = rem % 16;
    int ph = l / 14, pw = l % 14;
    col[idx] = tf32r(x[((b*3 + c)*224 + ph*16 + i)*224 + pw*16 + j]);
}

// ================= fused residual add + LayerNorm =================
__global__ void add_ln_kernel(const float* __restrict__ hidden, float* __restrict__ residual,
                              float* __restrict__ hn, const float* __restrict__ w,
                              const float* __restrict__ b, int first) {
    int row = blockIdx.x;
    int t = threadIdx.x;               // 192 threads
    int idx = row*D_MODEL + t;
    float h = hidden[idx];
    float r = first ? h : (residual[idx] + h);
    residual[idx] = r;
    __shared__ float red[6];
    float s = r;
    #pragma unroll
    for (int o = 16; o > 0; o >>= 1) s += __shfl_xor_sync(0xffffffffu, s, o);
    if ((t & 31) == 0) red[t >> 5] = s;
    __syncthreads();
    float mean = (red[0]+red[1]+red[2]+red[3]+red[4]+red[5]) * (1.f/192.f);
    __syncthreads();
    float dv = r - mean;
    s = dv*dv;
    #pragma unroll
    for (int o = 16; o > 0; o >>= 1) s += __shfl_xor_sync(0xffffffffu, s, o);
    if ((t & 31) == 0) red[t >> 5] = s;
    __syncthreads();
    float var = (red[0]+red[1]+red[2]+red[3]+red[4]+red[5]) * (1.f/192.f);
    hn[idx] = tf32r(dv * rsqrtf(var + 1e-5f) * w[t] + b[t]);
}

// ================= causal depthwise conv1d + SiLU, sliding window =================
__global__ __launch_bounds__(384) void conv_silu_kernel(
        const float* __restrict__ xz, const float* __restrict__ cw,
        const float* __restrict__ cb, float* __restrict__ xb) {
    int d = threadIdx.x;
    int b = blockIdx.x;
    int l0 = blockIdx.y * 49;
    float w0 = cw[d*D_CONV+0], w1 = cw[d*D_CONV+1], w2 = cw[d*D_CONV+2], w3 = cw[d*D_CONV+3];
    float bias = cb[d];
    size_t base = (size_t)b*L_SEQ*(2*D_INNER) + d;
    size_t obase = (size_t)b*L_SEQ*D_INNER + d;
    float xm3 = (l0 >= 3) ? xz[base + (size_t)(l0-3)*(2*D_INNER)] : 0.f;
    float xm2 = (l0 >= 2) ? xz[base + (size_t)(l0-2)*(2*D_INNER)] : 0.f;
    float xm1 = (l0 >= 1) ? xz[base + (size_t)(l0-1)*(2*D_INNER)] : 0.f;
    #pragma unroll 7
    for (int l = l0; l < l0 + 49; l++) {
        float x0 = xz[base + (size_t)l*(2*D_INNER)];
        float acc = bias + w0*xm3 + w1*xm2 + w2*xm1 + w3*x0;
        float sig = 1.f / (1.f + __expf(-acc));
        xb[obase + (size_t)l*D_INNER] = acc * sig;
        xm3 = xm2; xm2 = xm1; xm1 = x0;
    }
}

// ================= scan =================
__global__ __launch_bounds__(128) void scan_kernel(
        const float* __restrict__ xb, const float* __restrict__ xdbl,
        const float* __restrict__ xz, const float* __restrict__ A_log,
        const float* __restrict__ Dskip, const float* __restrict__ dtw,
        const float* __restrict__ dtb, float* __restrict__ y) {
    int b = blockIdx.y;
    int d = blockIdx.x * 128 + threadIdx.x;
    __shared__ float sdbl[L_SEQ][XPROJ_N];
    const float* src = &xdbl[(size_t)b*L_SEQ*XPROJ_N];
    for (int idx = threadIdx.x; idx < L_SEQ*XPROJ_N; idx += 128)
        ((float*)sdbl)[idx] = src[idx];
    __syncthreads();

    float wdt[DT_RANK];
    #pragma unroll
    for (int r = 0; r < DT_RANK; r++) wdt[r] = dtw[d*DT_RANK + r];
    float bdt = dtb[d];
    float a[D_STATE], h[D_STATE];
    #pragma unroll
    for (int n = 0; n < D_STATE; n++) {
        a[n] = -__expf(A_log[d*D_STATE + n]);
        h[n] = 0.f;
    }
    bool structured = true;
    #pragma unroll
    for (int n = 0; n < D_STATE; n++)
        structured = structured && (a[n] == a[0]*(float)(n+1));
    float Dd = Dskip[d];

    size_t base0 = (size_t)b*L_SEQ*D_INNER + d;
    size_t zbase0 = (size_t)b*L_SEQ*(2*D_INNER) + D_INNER + d;
    float u_cur = xb[base0];
    float z_cur = xz[zbase0];
    for (int l = 0; l < L_SEQ; l++) {
        float u = u_cur, z = z_cur;
        if (l + 1 < L_SEQ) {
            u_cur = xb[base0 + (size_t)(l+1)*D_INNER];
            z_cur = xz[zbase0 + (size_t)(l+1)*(2*D_INNER)];
        }
        float dt = bdt;
        #pragma unroll
        for (int r = 0; r < DT_RANK; r++) dt += sdbl[l][r] * wdt[r];
        dt = (dt > 15.f) ? dt : __logf(1.f + __expf(dt));
        float du = dt * u;
        float e[D_STATE];
        if (structured) {
            float w = __expf(dt * a[0]);
            e[0] = w;
            float w2 = w * w;
            e[1] = w2;
            float w4 = w2 * w2;
            e[2] = w2 * w;  e[3] = w4;
            e[4] = w4 * w;  e[5] = w4 * w2;  e[6] = w4 * e[2]; e[7] = w4 * w4;
            #pragma unroll
            for (int n = 8; n < D_STATE; n++) e[n] = e[7] * e[n - 8];
        } else {
            #pragma unroll
            for (int n = 0; n < D_STATE; n++) e[n] = __expf(dt * a[n]);
        }
        float yv = 0.f;
        #pragma unroll
        for (int n = 0; n < D_STATE; n++) {
            h[n] = e[n] * h[n] + du * sdbl[l][DT_RANK + n];
            yv  += h[n] * sdbl[l][DT_RANK + D_STATE + n];
        }
        yv += u * Dd;
        float sig = 1.f / (1.f + __expf(-z));
        y[base0 + (size_t)l*D_INNER] = tf32r(yv * (z * sig));
    }
}

// ================= final =================
__global__ void final_kernel(const float* __restrict__ residual, const float* __restrict__ hidden,
                             const float* __restrict__ nw, const float* __restrict__ nb,
                             const float* __restrict__ hw, const float* __restrict__ hb,
                             float* __restrict__ out) {
    int b = blockIdx.x;
    int t = threadIdx.x;               // 256 threads
    __shared__ float sh[D_MODEL];
    __shared__ float red[8];
    int row = b*L_SEQ + (L_SEQ - 1);
    float v = 0.f;
    if (t < D_MODEL) v = residual[row*D_MODEL + t] + hidden[row*D_MODEL + t];
    float s = v;
    #pragma unroll
    for (int o = 16; o > 0; o >>= 1) s += __shfl_xor_sync(0xffffffffu, s, o);
    if ((t & 31) == 0) red[t >> 5] = s;
    __syncthreads();
    float mean = 0.f;
    #pragma unroll
    for (int i = 0; i < 8; i++) mean += red[i];
    mean *= (1.f/192.f);
    __syncthreads();
    float dv = (t < D_MODEL) ? (v - mean) : 0.f;
    s = dv*dv;
    #pragma unroll
    for (int o = 16; o > 0; o >>= 1) s += __shfl_xor_sync(0xffffffffu, s, o);
    if ((t & 31) == 0) red[t >> 5] = s;
    __syncthreads();
    float var = 0.f;
    #pragma unroll
    for (int i = 0; i < 8; i++) var += red[i];
    var *= (1.f/192.f);
    if (t < D_MODEL) sh[t] = dv * rsqrtf(var + 1e-5f) * nw[t] + nb[t];
    __syncthreads();
    for (int o = t; o < N_CLS; o += 256) {
        float acc = hb[o];
        #pragma unroll 4
        for (int k = 0; k < D_MODEL; k++) acc += sh[k] * hw[o*D_MODEL + k];
        out[b*N_CLS + o] = acc;
    }
}

extern "C" void kernel_launch(void* const* d_in, const int* in_sizes, int n_in,
                              void* d_out, int out_size) {
    const float* x        = (const float*)d_in[0];
    const float* patch_w  = (const float*)d_in[1];
    const float* patch_b  = (const float*)d_in[2];
    const float* in_w     = (const float*)d_in[3];
    const float* conv_w   = (const float*)d_in[4];
    const float* conv_b   = (const float*)d_in[5];
    const float* xproj_w  = (const float*)d_in[6];
    const float* dt_w     = (const float*)d_in[7];
    const float* dt_b     = (const float*)d_in[8];
    const float* A_log    = (const float*)d_in[9];
    const float* D_skip   = (const float*)d_in[10];
    const float* out_w    = (const float*)d_in[11];
    const float* norm_w   = (const float*)d_in[12];
    const float* norm_b   = (const float*)d_in[13];
    const float* normf_w  = (const float*)d_in[14];
    const float* normf_b  = (const float*)d_in[15];
    const float* head_w   = (const float*)d_in[16];
    const float* head_b   = (const float*)d_in[17];
    float* out = (float*)d_out;

    float *hidden, *residual, *hn, *xz, *xb, *xdbl, *y;
    float *wpatch, *win, *wx, *wout;
    cudaGetSymbolAddress((void**)&hidden,   g_hidden);
    cudaGetSymbolAddress((void**)&residual, g_residual);
    cudaGetSymbolAddress((void**)&hn,       g_hn);
    cudaGetSymbolAddress((void**)&xz,       g_xz);
    cudaGetSymbolAddress((void**)&xb,       g_xb);
    cudaGetSymbolAddress((void**)&xdbl,     g_xdbl);
    cudaGetSymbolAddress((void**)&y,        g_y);
    cudaGetSymbolAddress((void**)&wpatch,   g_wpatch);
    cudaGetSymbolAddress((void**)&win,      g_win);
    cudaGetSymbolAddress((void**)&wx,       g_wx);
    cudaGetSymbolAddress((void**)&wout,     g_wout);

    cudaFuncSetAttribute(gemm_mma,  cudaFuncAttributeMaxDynamicSharedMemorySize, 2*STAGE_BYTES);
    cudaFuncSetAttribute(gemm_wide, cudaFuncAttributeMaxDynamicSharedMemorySize, 2*WIDE_STAGE);
    cudaFuncSetAttribute(gemm_x,    cudaFuncAttributeMaxDynamicSharedMemorySize, 2*X_STAGE);
    cudaFuncSetAttribute(gemm_mma,  cudaFuncAttributePreferredSharedMemoryCarveout, 100);
    cudaFuncSetAttribute(gemm_wide, cudaFuncAttributePreferredSharedMemoryCarveout, 100);
    cudaFuncSetAttribute(gemm_x,    cudaFuncAttributePreferredSharedMemoryCarveout, 100);

    // pre-round GEMM weights to tf32
    round_tf32_kernel<<<512, 256>>>(patch_w, wpatch, D_MODEL*K_PATCH);
    round_tf32_kernel<<<2048, 256>>>(in_w,   win,    DEPTH*2*D_INNER*D_MODEL);
    round_tf32_kernel<<<512, 256>>>(xproj_w, wx,     DEPTH*XPROJ_N*D_INNER);
    round_tf32_kernel<<<1024, 256>>>(out_w,  wout,   DEPTH*D_MODEL*D_INNER);

    // patch embed
    im2col_kernel<<<(ROWS*K_PATCH + 255)/256, 256>>>(x, xz);
    gemm_mma<<<dim3(3, ROWS/128), 256, 2*STAGE_BYTES>>>(xz, wpatch, hidden,
                                                        ROWS, D_MODEL, K_PATCH, patch_b);

    for (int i = 0; i < DEPTH; i++) {
        add_ln_kernel<<<ROWS, D_MODEL>>>(hidden, residual, hn,
                                         norm_w + (size_t)i*D_MODEL, norm_b + (size_t)i*D_MODEL, i == 0);
        gemm_wide<<<dim3(6, ROWS/128), 256, 2*WIDE_STAGE>>>(
            hn, win + (size_t)i*2*D_INNER*D_MODEL, xz, ROWS, 2*D_INNER, D_MODEL);
        conv_silu_kernel<<<dim3(B_SZ, 4), 384>>>(xz, conv_w + (size_t)i*D_INNER*D_CONV,
                                                 conv_b + (size_t)i*D_INNER, xb);
        gemm_x<<<ROWS/64, 256, 2*X_STAGE>>>(
            xb, wx + (size_t)i*XPROJ_N*D_INNER, xdbl, ROWS, XPROJ_N, D_INNER);
        scan_kernel<<<dim3(D_INNER/128, B_SZ), 128>>>(
            xb, xdbl, xz, A_log + (size_t)i*D_INNER*D_STATE, D_skip + (size_t)i*D_INNER,
            dt_w + (size_t)i*D_INNER*DT_RANK, dt_b + (size_t)i*D_INNER, y);
        gemm_mma<<<dim3(3, ROWS/128), 256, 2*STAGE_BYTES>>>(
            y, wout + (size_t)i*D_MODEL*D_INNER, hidden, ROWS, D_MODEL, D_INNER, nullptr);
    }

    final_kernel<<<B_SZ, 256>>>(residual, hidden, normf_w, normf_b, head_w, head_b, out);
}

// round 13
// speedup vs baseline: 1.0824x; 1.0384x over previous
#include <cuda_runtime.h>
#include <math.h>
#include <stdint.h>

#define B_SZ 64
#define L_SEQ 196
#define D_MODEL 192
#define DEPTH 24
#define D_INNER 384
#define D_STATE 16
#define D_CONV 4
#define DT_RANK 12
#define N_CLS 1000
#define XPROJ_N (DT_RANK + 2*D_STATE)   // 44
#define ROWS (B_SZ*L_SEQ)               // 12544
#define K_PATCH 768                      // 3*16*16

// ---------------- scratch ----------------
__device__ float g_hidden[ROWS*D_MODEL];
__device__ float g_residual[ROWS*D_MODEL];
__device__ float g_hn[ROWS*D_MODEL];
__device__ float g_xz[ROWS*2*D_INNER];
__device__ float g_xb[ROWS*D_INNER];
__device__ float g_xdbl[ROWS*XPROJ_N];
__device__ float g_y[ROWS*D_INNER];
__device__ float g_wpatch[D_MODEL*K_PATCH];
__device__ float g_win[DEPTH*2*D_INNER*D_MODEL];
__device__ float g_wx[DEPTH*XPROJ_N*D_INNER];
__device__ float g_wout[DEPTH*D_MODEL*D_INNER];

// ================= helpers =================
__device__ __forceinline__ uint32_t f2tf32(float f) {
    uint32_t o;
    asm("cvt.rna.tf32.f32 %0, %1;" : "=r"(o) : "f"(f));
    return o;
}
__device__ __forceinline__ float tf32r(float f) { return __uint_as_float(f2tf32(f)); }

__global__ void round_tf32_kernel(const float* __restrict__ src, float* __restrict__ dst, int n) {
    int i = blockIdx.x * blockDim.x + threadIdx.x;
    int stride = gridDim.x * blockDim.x;
    for (; i < n; i += stride) dst[i] = tf32r(src[i]);
}

__device__ __forceinline__ uint32_t smem_u32(const void* p) {
    uint32_t a;
    asm("{ .reg .u64 t; cvta.to.shared.u64 t, %1; cvt.u32.u64 %0, t; }" : "=r"(a) : "l"(p));
    return a;
}
#define CP_ASYNC(dst, src, sz) \
    asm volatile("cp.async.cg.shared.global [%0], [%1], 16, %2;" :: "r"(dst), "l"(src), "r"(sz))
#define CP_COMMIT() asm volatile("cp.async.commit_group;" ::: "memory")
#define CP_WAIT(n)  asm volatile("cp.async.wait_group %0;" :: "n"(n) : "memory")

__device__ __forceinline__ void mma1688(float* c, const uint32_t* a, const uint32_t* b) {
    asm volatile(
        "mma.sync.aligned.m16n8k8.row.col.f32.tf32.tf32.f32 "
        "{%0,%1,%2,%3}, {%4,%5,%6,%7}, {%8,%9}, {%0,%1,%2,%3};"
        : "+f"(c[0]), "+f"(c[1]), "+f"(c[2]), "+f"(c[3])
        : "r"(a[0]), "r"(a[1]), "r"(a[2]), "r"(a[3]), "r"(b[0]), "r"(b[1]));
}

#define GA_STRIDE 36

// ================= gemm_mma: BM=128, BN=64, BK=32 (out_proj/patch/x_proj) =================
#define STAGE_BYTES ((128+64)*GA_STRIDE*4)   // 27648
#define SMEM_W_OFF (128*GA_STRIDE)

__global__ __launch_bounds__(256, 3) void gemm_mma(
        const float* __restrict__ A, const float* __restrict__ W,
        float* __restrict__ C, int M, int N, int K,
        const float* __restrict__ bias) {
    extern __shared__ float smem[];
    int tid = threadIdx.x;
    int wid = tid >> 5, lid = tid & 31;
    int wm = wid & 3, wn = wid >> 2;
    int group = lid >> 2, tq = lid & 3;
    int bm = blockIdx.y * 128, bn = blockIdx.x * 64;
    uint32_t sb = smem_u32(smem);
    int nk = K >> 5;

    auto load_stage = [&](int st, int kc) {
        uint32_t base = sb + st * STAGE_BYTES;
        #pragma unroll
        for (int i = 0; i < 4; i++) {
            int q = tid * 4 + i;
            int row = q >> 3, quad = q & 7;
            uint32_t dst = base + (row * GA_STRIDE + quad * 4) * 4;
            const float* src = A + (size_t)(bm + row) * K + (size_t)kc * 32 + quad * 4;
            CP_ASYNC(dst, src, 16);
        }
        #pragma unroll
        for (int i = 0; i < 2; i++) {
            int q = tid * 2 + i;
            int row = q >> 3, quad = q & 7;
            int n = bn + row;
            uint32_t dst = base + (SMEM_W_OFF + row * GA_STRIDE + quad * 4) * 4;
            const float* src = (n < N) ? (W + (size_t)n * K + (size_t)kc * 32 + quad * 4) : W;
            CP_ASYNC(dst, src, (n < N) ? 16 : 0);
        }
        CP_COMMIT();
    };

    float acc[2][4][4] = {};
    load_stage(0, 0);
    for (int k0 = 0; k0 < nk; k0++) {
        if (k0 + 1 < nk) { load_stage((k0 + 1) & 1, k0 + 1); CP_WAIT(1); }
        else             { CP_WAIT(0); }
        __syncthreads();
        const float* sA = smem + (size_t)(k0 & 1) * (STAGE_BYTES / 4);
        const float* sW = sA + SMEM_W_OFF;
        #pragma unroll
        for (int kk = 0; kk < 32; kk += 8) {
            uint32_t a[2][4], b[4][2];
            #pragma unroll
            for (int mi = 0; mi < 2; mi++) {
                int r = wm * 32 + mi * 16 + group;
                a[mi][0] = __float_as_uint(sA[r * GA_STRIDE + kk + tq]);
                a[mi][1] = __float_as_uint(sA[(r + 8) * GA_STRIDE + kk + tq]);
                a[mi][2] = __float_as_uint(sA[r * GA_STRIDE + kk + tq + 4]);
                a[mi][3] = __float_as_uint(sA[(r + 8) * GA_STRIDE + kk + tq + 4]);
            }
            #pragma unroll
            for (int ni = 0; ni < 4; ni++) {
                int r = wn * 32 + ni * 8 + group;
                b[ni][0] = __float_as_uint(sW[r * GA_STRIDE + kk + tq]);
                b[ni][1] = __float_as_uint(sW[r * GA_STRIDE + kk + tq + 4]);
            }
            #pragma unroll
            for (int mi = 0; mi < 2; mi++)
                #pragma unroll
                for (int ni = 0; ni < 4; ni++)
                    mma1688(acc[mi][ni], a[mi], b[ni]);
        }
        __syncthreads();
    }
    #pragma unroll
    for (int mi = 0; mi < 2; mi++) {
        int m0 = bm + wm * 32 + mi * 16 + group;
        #pragma unroll
        for (int ni = 0; ni < 4; ni++) {
            int n0 = bn + wn * 32 + ni * 8 + tq * 2;
            if (n0 < N) {
                float bx = 0.f, by = 0.f;
                if (bias) { bx = bias[n0]; by = bias[n0 + 1]; }
                float2 o0 = make_float2(acc[mi][ni][0] + bx, acc[mi][ni][1] + by);
                float2 o1 = make_float2(acc[mi][ni][2] + bx, acc[mi][ni][3] + by);
                *(float2*)&C[(size_t)m0 * N + n0] = o0;
                *(float2*)&C[(size_t)(m0 + 8) * N + n0] = o1;
            }
        }
    }
}

// ================= gemm_wide: BM=128, BN=128, BK=32, 3-stage single-sync (in_proj) =================
#define WIDE_STAGE ((128+128)*GA_STRIDE*4)   // 36864
#define WIDE_W_OFF (128*GA_STRIDE)

__global__ __launch_bounds__(256, 2) void gemm_wide(
        const float* __restrict__ A, const float* __restrict__ W,
        float* __restrict__ C, int M, int N, int K) {
    extern __shared__ float smem[];
    int tid = threadIdx.x;
    int wid = tid >> 5, lid = tid & 31;
    int wm = wid & 3, wn = wid >> 2;          // 4 x 2; warp tile 32 x 64
    int group = lid >> 2, tq = lid & 3;
    int bm = blockIdx.y * 128, bn = blockIdx.x * 128;
    uint32_t sb = smem_u32(smem);
    int nk = K >> 5;                          // >= 2 at all call sites (K=192)

    auto load_stage = [&](int st, int kc) {
        uint32_t base = sb + st * WIDE_STAGE;
        #pragma unroll
        for (int i = 0; i < 4; i++) {
            int q = tid * 4 + i;
            int row = q >> 3, quad = q & 7;
            uint32_t dst = base + (row * GA_STRIDE + quad * 4) * 4;
            const float* src = A + (size_t)(bm + row) * K + (size_t)kc * 32 + quad * 4;
            CP_ASYNC(dst, src, 16);
        }
        #pragma unroll
        for (int i = 0; i < 4; i++) {
            int q = tid * 4 + i;
            int row = q >> 3, quad = q & 7;
            int n = bn + row;
            uint32_t dst = base + (WIDE_W_OFF + row * GA_STRIDE + quad * 4) * 4;
            const float* src = (n < N) ? (W + (size_t)n * K + (size_t)kc * 32 + quad * 4) : W;
            CP_ASYNC(dst, src, (n < N) ? 16 : 0);
        }
        CP_COMMIT();
    };

    float acc[2][8][4] = {};
    load_stage(0, 0);
    load_stage(1, 1);
    for (int k0 = 0; k0 < nk; k0++) {
        // wait for group k0 (one per stage): issued so far = min(nk, k0+2)
        if (k0 < nk - 1) CP_WAIT(1);
        else             CP_WAIT(0);
        __syncthreads();                       // stage k0 visible; compute(k0-1) done by all
        if (k0 + 2 < nk) load_stage((k0 + 2) % 3, k0 + 2);   // overwrites buf (k0-1)%3 — safe
        const float* sA = smem + (size_t)(k0 % 3) * (WIDE_STAGE / 4);
        const float* sW = sA + WIDE_W_OFF;
        #pragma unroll
        for (int kk = 0; kk < 32; kk += 8) {
            uint32_t a[2][4], b[8][2];
            #pragma unroll
            for (int mi = 0; mi < 2; mi++) {
                int r = wm * 32 + mi * 16 + group;
                a[mi][0] = __float_as_uint(sA[r * GA_STRIDE + kk + tq]);
                a[mi][1] = __float_as_uint(sA[(r + 8) * GA_STRIDE + kk + tq]);
                a[mi][2] = __float_as_uint(sA[r * GA_STRIDE + kk + tq + 4]);
                a[mi][3] = __float_as_uint(sA[(r + 8) * GA_STRIDE + kk + tq + 4]);
            }
            #pragma unroll
            for (int ni = 0; ni < 8; ni++) {
                int r = wn * 64 + ni * 8 + group;
                b[ni][0] = __float_as_uint(sW[r * GA_STRIDE + kk + tq]);
                b[ni][1] = __float_as_uint(sW[r * GA_STRIDE + kk + tq + 4]);
            }
            #pragma unroll
            for (int mi = 0; mi < 2; mi++)
                #pragma unroll
                for (int ni = 0; ni < 8; ni++)
                    mma1688(acc[mi][ni], a[mi], b[ni]);
        }
    }
    #pragma unroll
    for (int mi = 0; mi < 2; mi++) {
        int m0 = bm + wm * 32 + mi * 16 + group;
        #pragma unroll
        for (int ni = 0; ni < 8; ni++) {
            int n0 = bn + wn * 64 + ni * 8 + tq * 2;
            if (n0 < N) {
                *(float2*)&C[(size_t)m0 * N + n0] = make_float2(acc[mi][ni][0], acc[mi][ni][1]);
                *(float2*)&C[(size_t)(m0 + 8) * N + n0] = make_float2(acc[mi][ni][2], acc[mi][ni][3]);
            }
        }
    }
}

// ================= im2col =================
__global__ void im2col_kernel(const float* __restrict__ x, float* __restrict__ col) {
    int idx = blockIdx.x * blockDim.x + threadIdx.x;
    if (idx >= ROWS * K_PATCH) return;
    int k  = idx % K_PATCH;
    int bl = idx / K_PATCH;
    int l  = bl % L_SEQ;
    int b  = bl / L_SEQ;
    int c  = k / 256;
    int rem = k % 256;
    int i = rem / 16, j = rem % 16;
    int ph = l / 14, pw = l % 14;
    col[idx] = tf32r(x[((b*3 + c)*224 + ph*16 + i)*224 + pw*16 + j]);
}

// ================= warp-per-row residual add + LayerNorm =================
// block 256 = 8 warps = 8 rows; shuffle-only reductions, no block barrier
__global__ __launch_bounds__(256) void add_ln_kernel(
        const float* __restrict__ hidden, float* __restrict__ residual,
        float* __restrict__ hn, const float* __restrict__ w,
        const float* __restrict__ b, int first) {
    int warp = threadIdx.x >> 5, lane = threadIdx.x & 31;
    int row = blockIdx.x * 8 + warp;
    size_t base = (size_t)row * D_MODEL;
    float v[6];
    float sum = 0.f;
    #pragma unroll
    for (int j = 0; j < 6; j++) {
        int c = lane + j*32;
        float h = hidden[base + c];
        float r = first ? h : (residual[base + c] + h);
        v[j] = r;
        residual[base + c] = r;
        sum += r;
    }
    #pragma unroll
    for (int o = 16; o > 0; o >>= 1) sum += __shfl_xor_sync(0xffffffffu, sum, o);
    float mean = sum * (1.f/192.f);
    float sq = 0.f;
    #pragma unroll
    for (int j = 0; j < 6; j++) { float d = v[j] - mean; sq += d*d; }
    #pragma unroll
    for (int o = 16; o > 0; o >>= 1) sq += __shfl_xor_sync(0xffffffffu, sq, o);
    float rstd = rsqrtf(sq * (1.f/192.f) + 1e-5f);
    #pragma unroll
    for (int j = 0; j < 6; j++) {
        int c = lane + j*32;
        hn[base + c] = tf32r((v[j] - mean) * rstd * w[c] + b[c]);
    }
}

// ================= causal depthwise conv1d + SiLU, sliding window =================
__global__ __launch_bounds__(384) void conv_silu_kernel(
        const float* __restrict__ xz, const float* __restrict__ cw,
        const float* __restrict__ cb, float* __restrict__ xb) {
    int d = threadIdx.x;
    int b = blockIdx.x;
    int l0 = blockIdx.y * 49;
    float w0 = cw[d*D_CONV+0], w1 = cw[d*D_CONV+1], w2 = cw[d*D_CONV+2], w3 = cw[d*D_CONV+3];
    float bias = cb[d];
    size_t base = (size_t)b*L_SEQ*(2*D_INNER) + d;
    size_t obase = (size_t)b*L_SEQ*D_INNER + d;
    float xm3 = (l0 >= 3) ? xz[base + (size_t)(l0-3)*(2*D_INNER)] : 0.f;
    float xm2 = (l0 >= 2) ? xz[base + (size_t)(l0-2)*(2*D_INNER)] : 0.f;
    float xm1 = (l0 >= 1) ? xz[base + (size_t)(l0-1)*(2*D_INNER)] : 0.f;
    #pragma unroll 7
    for (int l = l0; l < l0 + 49; l++) {
        float x0 = xz[base + (size_t)l*(2*D_INNER)];
        float acc = bias + w0*xm3 + w1*xm2 + w2*xm1 + w3*x0;
        float sig = 1.f / (1.f + __expf(-acc));
        xb[obase + (size_t)l*D_INNER] = acc * sig;
        xm3 = xm2; xm2 = xm1; xm1 = x0;
    }
}

// ================= scan =================
__global__ __launch_bounds__(128) void scan_kernel(
        const float* __restrict__ xb, const float* __restrict__ xdbl,
        const float* __restrict__ xz, const float* __restrict__ A_log,
        const float* __restrict__ Dskip, const float* __restrict__ dtw,
        const float* __restrict__ dtb, float* __restrict__ y) {
    int b = blockIdx.y;
    int d = blockIdx.x * 128 + threadIdx.x;
    __shared__ float sdbl[L_SEQ][XPROJ_N];
    const float* src = &xdbl[(size_t)b*L_SEQ*XPROJ_N];
    for (int idx = threadIdx.x; idx < L_SEQ*XPROJ_N; idx += 128)
        ((float*)sdbl)[idx] = src[idx];
    __syncthreads();

    float wdt[DT_RANK];
    #pragma unroll
    for (int r = 0; r < DT_RANK; r++) wdt[r] = dtw[d*DT_RANK + r];
    float bdt = dtb[d];
    float a[D_STATE], h[D_STATE];
    #pragma unroll
    for (int n = 0; n < D_STATE; n++) {
        a[n] = -__expf(A_log[d*D_STATE + n]);
        h[n] = 0.f;
    }
    bool structured = true;
    #pragma unroll
    for (int n = 0; n < D_STATE; n++)
        structured = structured && (a[n] == a[0]*(float)(n+1));
    float Dd = Dskip[d];

    size_t base0 = (size_t)b*L_SEQ*D_INNER + d;
    size_t zbase0 = (size_t)b*L_SEQ*(2*D_INNER) + D_INNER + d;
    float u_cur = xb[base0];
    float z_cur = xz[zbase0];
    for (int l = 0; l < L_SEQ; l++) {
        float u = u_cur, z = z_cur;
        if (l + 1 < L_SEQ) {
            u_cur = xb[base0 + (size_t)(l+1)*D_INNER];
            z_cur = xz[zbase0 + (size_t)(l+1)*(2*D_INNER)];
        }
        float dt = bdt;
        #pragma unroll
        for (int r = 0; r < DT_RANK; r++) dt += sdbl[l][r] * wdt[r];
        dt = (dt > 15.f) ? dt : __logf(1.f + __expf(dt));
        float du = dt * u;
        float e[D_STATE];
        if (structured) {
            float w = __expf(dt * a[0]);
            e[0] = w;
            float w2 = w * w;
            e[1] = w2;
            float w4 = w2 * w2;
            e[2] = w2 * w;  e[3] = w4;
            e[4] = w4 * w;  e[5] = w4 * w2;  e[6] = w4 * e[2]; e[7] = w4 * w4;
            #pragma unroll
            for (int n = 8; n < D_STATE; n++) e[n] = e[7] * e[n - 8];
        } else {
            #pragma unroll
            for (int n = 0; n < D_STATE; n++) e[n] = __expf(dt * a[n]);
        }
        float yv = 0.f;
        #pragma unroll
        for (int n = 0; n < D_STATE; n++) {
            h[n] = e[n] * h[n] + du * sdbl[l][DT_RANK + n];
            yv  += h[n] * sdbl[l][DT_RANK + D_STATE + n];
        }
        yv += u * Dd;
        float sig = 1.f / (1.f + __expf(-z));
        y[base0 + (size_t)l*D_INNER] = tf32r(yv * (z * sig));
    }
}

// ================= final =================
__global__ void final_kernel(const float* __restrict__ residual, const float* __restrict__ hidden,
                             const float* __restrict__ nw, const float* __restrict__ nb,
                             const float* __restrict__ hw, const float* __restrict__ hb,
                             float* __restrict__ out) {
    int b = blockIdx.x;
    int t = threadIdx.x;               // 256 threads
    __shared__ float sh[D_MODEL];
    __shared__ float red[8];
    int row = b*L_SEQ + (L_SEQ - 1);
    float v = 0.f;
    if (t < D_MODEL) v = residual[row*D_MODEL + t] + hidden[row*D_MODEL + t];
    float s = v;
    #pragma unroll
    for (int o = 16; o > 0; o >>= 1) s += __shfl_xor_sync(0xffffffffu, s, o);
    if ((t & 31) == 0) red[t >> 5] = s;
    __syncthreads();
    float mean = 0.f;
    #pragma unroll
    for (int i = 0; i < 8; i++) mean += red[i];
    mean *= (1.f/192.f);
    __syncthreads();
    float dv = (t < D_MODEL) ? (v - mean) : 0.f;
    s = dv*dv;
    #pragma unroll
    for (int o = 16; o > 0; o >>= 1) s += __shfl_xor_sync(0xffffffffu, s, o);
    if ((t & 31) == 0) red[t >> 5] = s;
    __syncthreads();
    float var = 0.f;
    #pragma unroll
    for (int i = 0; i < 8; i++) var += red[i];
    var *= (1.f/192.f);
    if (t < D_MODEL) sh[t] = dv * rsqrtf(var + 1e-5f) * nw[t] + nb[t];
    __syncthreads();
    for (int o = t; o < N_CLS; o += 256) {
        float acc = hb[o];
        #pragma unroll 4
        for (int k = 0; k < D_MODEL; k++) acc += sh[k] * hw[o*D_MODEL + k];
        out[b*N_CLS + o] = acc;
    }
}

extern "C" void kernel_launch(void* const* d_in, const int* in_sizes, int n_in,
                              void* d_out, int out_size) {
    const float* x        = (const float*)d_in[0];
    const float* patch_w  = (const float*)d_in[1];
    const float* patch_b  = (const float*)d_in[2];
    const float* in_w     = (const float*)d_in[3];
    const float* conv_w   = (const float*)d_in[4];
    const float* conv_b   = (const float*)d_in[5];
    const float* xproj_w  = (const float*)d_in[6];
    const float* dt_w     = (const float*)d_in[7];
    const float* dt_b     = (const float*)d_in[8];
    const float* A_log    = (const float*)d_in[9];
    const float* D_skip   = (const float*)d_in[10];
    const float* out_w    = (const float*)d_in[11];
    const float* norm_w   = (const float*)d_in[12];
    const float* norm_b   = (const float*)d_in[13];
    const float* normf_w  = (const float*)d_in[14];
    const float* normf_b  = (const float*)d_in[15];
    const float* head_w   = (const float*)d_in[16];
    const float* head_b   = (const float*)d_in[17];
    float* out = (float*)d_out;

    float *hidden, *residual, *hn, *xz, *xb, *xdbl, *y;
    float *wpatch, *win, *wx, *wout;
    cudaGetSymbolAddress((void**)&hidden,   g_hidden);
    cudaGetSymbolAddress((void**)&residual, g_residual);
    cudaGetSymbolAddress((void**)&hn,       g_hn);
    cudaGetSymbolAddress((void**)&xz,       g_xz);
    cudaGetSymbolAddress((void**)&xb,       g_xb);
    cudaGetSymbolAddress((void**)&xdbl,     g_xdbl);
    cudaGetSymbolAddress((void**)&y,        g_y);
    cudaGetSymbolAddress((void**)&wpatch,   g_wpatch);
    cudaGetSymbolAddress((void**)&win,      g_win);
    cudaGetSymbolAddress((void**)&wx,       g_wx);
    cudaGetSymbolAddress((void**)&wout,     g_wout);

    cudaFuncSetAttribute(gemm_mma,  cudaFuncAttributeMaxDynamicSharedMemorySize, 2*STAGE_BYTES);
    cudaFuncSetAttribute(gemm_wide, cudaFuncAttributeMaxDynamicSharedMemorySize, 3*WIDE_STAGE);
    cudaFuncSetAttribute(gemm_mma,  cudaFuncAttributePreferredSharedMemoryCarveout, 100);
    cudaFuncSetAttribute(gemm_wide, cudaFuncAttributePreferredSharedMemoryCarveout, 100);

    // pre-round GEMM weights to tf32
    round_tf32_kernel<<<512, 256>>>(patch_w, wpatch, D_MODEL*K_PATCH);
    round_tf32_kernel<<<2048, 256>>>(in_w,   win,    DEPTH*2*D_INNER*D_MODEL);
    round_tf32_kernel<<<512, 256>>>(xproj_w, wx,     DEPTH*XPROJ_N*D_INNER);
    round_tf32_kernel<<<1024, 256>>>(out_w,  wout,   DEPTH*D_MODEL*D_INNER);

    // patch embed
    im2col_kernel<<<(ROWS*K_PATCH + 255)/256, 256>>>(x, xz);
    gemm_mma<<<dim3(3, ROWS/128), 256, 2*STAGE_BYTES>>>(xz, wpatch, hidden,
                                                        ROWS, D_MODEL, K_PATCH, patch_b);

    for (int i = 0; i < DEPTH; i++) {
        add_ln_kernel<<<ROWS/8, 256>>>(hidden, residual, hn,
                                       norm_w + (size_t)i*D_MODEL, norm_b + (size_t)i*D_MODEL, i == 0);
        gemm_wide<<<dim3(6, ROWS/128), 256, 3*WIDE_STAGE>>>(
            hn, win + (size_t)i*2*D_INNER*D_MODEL, xz, ROWS, 2*D_INNER, D_MODEL);
        conv_silu_kernel<<<dim3(B_SZ, 4), 384>>>(xz, conv_w + (size_t)i*D_INNER*D_CONV,
                                                 conv_b + (size_t)i*D_INNER, xb);
        gemm_mma<<<dim3(1, ROWS/128), 256, 2*STAGE_BYTES>>>(
            xb, wx + (size_t)i*XPROJ_N*D_INNER, xdbl, ROWS, XPROJ_N, D_INNER, nullptr);
        scan_kernel<<<dim3(D_INNER/128, B_SZ), 128>>>(
            xb, xdbl, xz, A_log + (size_t)i*D_INNER*D_STATE, D_skip + (size_t)i*D_INNER,
            dt_w + (size_t)i*D_INNER*DT_RANK, dt_b + (size_t)i*D_INNER, y);
        gemm_mma<<<dim3(3, ROWS/128), 256, 2*STAGE_BYTES>>>(
            y, wout + (size_t)i*D_MODEL*D_INNER, hidden, ROWS, D_MODEL, D_INNER, nullptr);
    }

    final_kernel<<<B_SZ, 256>>>(residual, hidden, normf_w, normf_b, head_w, head_b, out);
}

// round 14
// speedup vs baseline: 1.1049x; 1.0208x over previous
#include <cuda_runtime.h>
#include <math.h>
#include <stdint.h>

#define B_SZ 64
#define L_SEQ 196
#define D_MODEL 192
#define DEPTH 24
#define D_INNER 384
#define D_STATE 16
#define D_CONV 4
#define DT_RANK 12
#define N_CLS 1000
#define XPROJ_N (DT_RANK + 2*D_STATE)   // 44
#define ROWS (B_SZ*L_SEQ)               // 12544
#define K_PATCH 768                      // 3*16*16

// ---------------- scratch ----------------
__device__ float g_hidden[ROWS*D_MODEL];
__device__ float g_residual[ROWS*D_MODEL];
__device__ float g_hn[ROWS*D_MODEL];
__device__ float g_xz[ROWS*2*D_INNER];
__device__ float g_xb[ROWS*D_INNER];
__device__ float g_xdbl[ROWS*XPROJ_N];
__device__ float g_y[ROWS*D_INNER];
__device__ float g_wpatch[D_MODEL*K_PATCH];
__device__ float g_win[DEPTH*2*D_INNER*D_MODEL];
__device__ float g_wx[DEPTH*XPROJ_N*D_INNER];
__device__ float g_wout[DEPTH*D_MODEL*D_INNER];

// ================= helpers =================
__device__ __forceinline__ uint32_t f2tf32(float f) {
    uint32_t o;
    asm("cvt.rna.tf32.f32 %0, %1;" : "=r"(o) : "f"(f));
    return o;
}
__device__ __forceinline__ float tf32r(float f) { return __uint_as_float(f2tf32(f)); }

__global__ void round_tf32_kernel(const float* __restrict__ src, float* __restrict__ dst, int n) {
    int i = blockIdx.x * blockDim.x + threadIdx.x;
    int stride = gridDim.x * blockDim.x;
    for (; i < n; i += stride) dst[i] = tf32r(src[i]);
}

__device__ __forceinline__ uint32_t smem_u32(const void* p) {
    uint32_t a;
    asm("{ .reg .u64 t; cvta.to.shared.u64 t, %1; cvt.u32.u64 %0, t; }" : "=r"(a) : "l"(p));
    return a;
}
#define CP_ASYNC(dst, src, sz) \
    asm volatile("cp.async.cg.shared.global [%0], [%1], 16, %2;" :: "r"(dst), "l"(src), "r"(sz))
#define CP_COMMIT() asm volatile("cp.async.commit_group;" ::: "memory")
#define CP_WAIT(n)  asm volatile("cp.async.wait_group %0;" :: "n"(n) : "memory")

__device__ __forceinline__ void mma1688(float* c, const uint32_t* a, const uint32_t* b) {
    asm volatile(
        "mma.sync.aligned.m16n8k8.row.col.f32.tf32.tf32.f32 "
        "{%0,%1,%2,%3}, {%4,%5,%6,%7}, {%8,%9}, {%0,%1,%2,%3};"
        : "+f"(c[0]), "+f"(c[1]), "+f"(c[2]), "+f"(c[3])
        : "r"(a[0]), "r"(a[1]), "r"(a[2]), "r"(a[3]), "r"(b[0]), "r"(b[1]));
}

#define GA_STRIDE 36

// ================= gemm_mma: BM=128, BN=64, BK=32, single-sync 2-stage =================
#define STAGE_BYTES ((128+64)*GA_STRIDE*4)   // 27648
#define SMEM_W_OFF (128*GA_STRIDE)

__global__ __launch_bounds__(256, 3) void gemm_mma(
        const float* __restrict__ A, const float* __restrict__ W,
        float* __restrict__ C, int M, int N, int K,
        const float* __restrict__ bias) {
    extern __shared__ float smem[];
    int tid = threadIdx.x;
    int wid = tid >> 5, lid = tid & 31;
    int wm = wid & 3, wn = wid >> 2;
    int group = lid >> 2, tq = lid & 3;
    int bm = blockIdx.y * 128, bn = blockIdx.x * 64;
    uint32_t sb = smem_u32(smem);
    int nk = K >> 5;

    auto load_stage = [&](int st, int kc) {
        uint32_t base = sb + st * STAGE_BYTES;
        #pragma unroll
        for (int i = 0; i < 4; i++) {
            int q = tid * 4 + i;
            int row = q >> 3, quad = q & 7;
            uint32_t dst = base + (row * GA_STRIDE + quad * 4) * 4;
            const float* src = A + (size_t)(bm + row) * K + (size_t)kc * 32 + quad * 4;
            CP_ASYNC(dst, src, 16);
        }
        #pragma unroll
        for (int i = 0; i < 2; i++) {
            int q = tid * 2 + i;
            int row = q >> 3, quad = q & 7;
            int n = bn + row;
            uint32_t dst = base + (SMEM_W_OFF + row * GA_STRIDE + quad * 4) * 4;
            const float* src = (n < N) ? (W + (size_t)n * K + (size_t)kc * 32 + quad * 4) : W;
            CP_ASYNC(dst, src, (n < N) ? 16 : 0);
        }
        CP_COMMIT();
    };

    float acc[2][4][4] = {};
    load_stage(0, 0);
    for (int k0 = 0; k0 < nk; k0++) {
        CP_WAIT(0);                           // stage k0 ready (only pending group)
        __syncthreads();                      // all threads done computing k0-1
        if (k0 + 1 < nk) load_stage((k0 + 1) & 1, k0 + 1);  // overwrites buf of k0-1 — safe
        const float* sA = smem + (size_t)(k0 & 1) * (STAGE_BYTES / 4);
        const float* sW = sA + SMEM_W_OFF;
        #pragma unroll
        for (int kk = 0; kk < 32; kk += 8) {
            uint32_t a[2][4], b[4][2];
            #pragma unroll
            for (int mi = 0; mi < 2; mi++) {
                int r = wm * 32 + mi * 16 + group;
                a[mi][0] = __float_as_uint(sA[r * GA_STRIDE + kk + tq]);
                a[mi][1] = __float_as_uint(sA[(r + 8) * GA_STRIDE + kk + tq]);
                a[mi][2] = __float_as_uint(sA[r * GA_STRIDE + kk + tq + 4]);
                a[mi][3] = __float_as_uint(sA[(r + 8) * GA_STRIDE + kk + tq + 4]);
            }
            #pragma unroll
            for (int ni = 0; ni < 4; ni++) {
                int r = wn * 32 + ni * 8 + group;
                b[ni][0] = __float_as_uint(sW[r * GA_STRIDE + kk + tq]);
                b[ni][1] = __float_as_uint(sW[r * GA_STRIDE + kk + tq + 4]);
            }
            #pragma unroll
            for (int mi = 0; mi < 2; mi++)
                #pragma unroll
                for (int ni = 0; ni < 4; ni++)
                    mma1688(acc[mi][ni], a[mi], b[ni]);
        }
    }
    #pragma unroll
    for (int mi = 0; mi < 2; mi++) {
        int m0 = bm + wm * 32 + mi * 16 + group;
        #pragma unroll
        for (int ni = 0; ni < 4; ni++) {
            int n0 = bn + wn * 32 + ni * 8 + tq * 2;
            if (n0 < N) {
                float bx = 0.f, by = 0.f;
                if (bias) { bx = bias[n0]; by = bias[n0 + 1]; }
                float2 o0 = make_float2(acc[mi][ni][0] + bx, acc[mi][ni][1] + by);
                float2 o1 = make_float2(acc[mi][ni][2] + bx, acc[mi][ni][3] + by);
                *(float2*)&C[(size_t)m0 * N + n0] = o0;
                *(float2*)&C[(size_t)(m0 + 8) * N + n0] = o1;
            }
        }
    }
}

// ================= gemm_wide: BM=128, BN=128, BK=32, 3-stage single-sync (in_proj) =================
#define WIDE_STAGE ((128+128)*GA_STRIDE*4)   // 36864
#define WIDE_W_OFF (128*GA_STRIDE)

__global__ __launch_bounds__(256, 2) void gemm_wide(
        const float* __restrict__ A, const float* __restrict__ W,
        float* __restrict__ C, int M, int N, int K) {
    extern __shared__ float smem[];
    int tid = threadIdx.x;
    int wid = tid >> 5, lid = tid & 31;
    int wm = wid & 3, wn = wid >> 2;          // 4 x 2; warp tile 32 x 64
    int group = lid >> 2, tq = lid & 3;
    int bm = blockIdx.y * 128, bn = blockIdx.x * 128;
    uint32_t sb = smem_u32(smem);
    int nk = K >> 5;

    auto load_stage = [&](int st, int kc) {
        uint32_t base = sb + st * WIDE_STAGE;
        #pragma unroll
        for (int i = 0; i < 4; i++) {
            int q = tid * 4 + i;
            int row = q >> 3, quad = q & 7;
            uint32_t dst = base + (row * GA_STRIDE + quad * 4) * 4;
            const float* src = A + (size_t)(bm + row) * K + (size_t)kc * 32 + quad * 4;
            CP_ASYNC(dst, src, 16);
        }
        #pragma unroll
        for (int i = 0; i < 4; i++) {
            int q = tid * 4 + i;
            int row = q >> 3, quad = q & 7;
            int n = bn + row;
            uint32_t dst = base + (WIDE_W_OFF + row * GA_STRIDE + quad * 4) * 4;
            const float* src = (n < N) ? (W + (size_t)n * K + (size_t)kc * 32 + quad * 4) : W;
            CP_ASYNC(dst, src, (n < N) ? 16 : 0);
        }
        CP_COMMIT();
    };

    float acc[2][8][4] = {};
    load_stage(0, 0);
    load_stage(1, 1);
    for (int k0 = 0; k0 < nk; k0++) {
        if (k0 < nk - 1) CP_WAIT(1);
        else             CP_WAIT(0);
        __syncthreads();
        if (k0 + 2 < nk) load_stage((k0 + 2) % 3, k0 + 2);
        const float* sA = smem + (size_t)(k0 % 3) * (WIDE_STAGE / 4);
        const float* sW = sA + WIDE_W_OFF;
        #pragma unroll
        for (int kk = 0; kk < 32; kk += 8) {
            uint32_t a[2][4], b[8][2];
            #pragma unroll
            for (int mi = 0; mi < 2; mi++) {
                int r = wm * 32 + mi * 16 + group;
                a[mi][0] = __float_as_uint(sA[r * GA_STRIDE + kk + tq]);
                a[mi][1] = __float_as_uint(sA[(r + 8) * GA_STRIDE + kk + tq]);
                a[mi][2] = __float_as_uint(sA[r * GA_STRIDE + kk + tq + 4]);
                a[mi][3] = __float_as_uint(sA[(r + 8) * GA_STRIDE + kk + tq + 4]);
            }
            #pragma unroll
            for (int ni = 0; ni < 8; ni++) {
                int r = wn * 64 + ni * 8 + group;
                b[ni][0] = __float_as_uint(sW[r * GA_STRIDE + kk + tq]);
                b[ni][1] = __float_as_uint(sW[r * GA_STRIDE + kk + tq + 4]);
            }
            #pragma unroll
            for (int mi = 0; mi < 2; mi++)
                #pragma unroll
                for (int ni = 0; ni < 8; ni++)
                    mma1688(acc[mi][ni], a[mi], b[ni]);
        }
    }
    #pragma unroll
    for (int mi = 0; mi < 2; mi++) {
        int m0 = bm + wm * 32 + mi * 16 + group;
        #pragma unroll
        for (int ni = 0; ni < 8; ni++) {
            int n0 = bn + wn * 64 + ni * 8 + tq * 2;
            if (n0 < N) {
                *(float2*)&C[(size_t)m0 * N + n0] = make_float2(acc[mi][ni][0], acc[mi][ni][1]);
                *(float2*)&C[(size_t)(m0 + 8) * N + n0] = make_float2(acc[mi][ni][2], acc[mi][ni][3]);
            }
        }
    }
}

// ================= im2col =================
__global__ void im2col_kernel(const float* __restrict__ x, float* __restrict__ col) {
    int idx = blockIdx.x * blockDim.x + threadIdx.x;
    if (idx >= ROWS * K_PATCH) return;
    int k  = idx % K_PATCH;
    int bl = idx / K_PATCH;
    int l  = bl % L_SEQ;
    int b  = bl / L_SEQ;
    int c  = k / 256;
    int rem = k % 256;
    int i = rem / 16, j = rem % 16;
    int ph = l / 14, pw = l % 14;
    col[idx] = tf32r(x[((b*3 + c)*224 + ph*16 + i)*224 + pw*16 + j]);
}

// ================= warp-per-row residual add + LayerNorm =================
__global__ __launch_bounds__(256) void add_ln_kernel(
        const float* __restrict__ hidden, float* __restrict__ residual,
        float* __restrict__ hn, const float* __restrict__ w,
        const float* __restrict__ b, int first) {
    int warp = threadIdx.x >> 5, lane = threadIdx.x & 31;
    int row = blockIdx.x * 8 + warp;
    size_t base = (size_t)row * D_MODEL;
    float v[6];
    float sum = 0.f;
    #pragma unroll
    for (int j = 0; j < 6; j++) {
        int c = lane + j*32;
        float h = hidden[base + c];
        float r = first ? h : (residual[base + c] + h);
        v[j] = r;
        residual[base + c] = r;
        sum += r;
    }
    #pragma unroll
    for (int o = 16; o > 0; o >>= 1) sum += __shfl_xor_sync(0xffffffffu, sum, o);
    float mean = sum * (1.f/192.f);
    float sq = 0.f;
    #pragma unroll
    for (int j = 0; j < 6; j++) { float d = v[j] - mean; sq += d*d; }
    #pragma unroll
    for (int o = 16; o > 0; o >>= 1) sq += __shfl_xor_sync(0xffffffffu, sq, o);
    float rstd = rsqrtf(sq * (1.f/192.f) + 1e-5f);
    #pragma unroll
    for (int j = 0; j < 6; j++) {
        int c = lane + j*32;
        hn[base + c] = tf32r((v[j] - mean) * rstd * w[c] + b[c]);
    }
}

// ================= causal depthwise conv1d + SiLU, sliding window =================
__global__ __launch_bounds__(384) void conv_silu_kernel(
        const float* __restrict__ xz, const float* __restrict__ cw,
        const float* __restrict__ cb, float* __restrict__ xb) {
    int d = threadIdx.x;
    int b = blockIdx.x;
    int l0 = blockIdx.y * 49;
    float w0 = cw[d*D_CONV+0], w1 = cw[d*D_CONV+1], w2 = cw[d*D_CONV+2], w3 = cw[d*D_CONV+3];
    float bias = cb[d];
    size_t base = (size_t)b*L_SEQ*(2*D_INNER) + d;
    size_t obase = (size_t)b*L_SEQ*D_INNER + d;
    float xm3 = (l0 >= 3) ? xz[base + (size_t)(l0-3)*(2*D_INNER)] : 0.f;
    float xm2 = (l0 >= 2) ? xz[base + (size_t)(l0-2)*(2*D_INNER)] : 0.f;
    float xm1 = (l0 >= 1) ? xz[base + (size_t)(l0-1)*(2*D_INNER)] : 0.f;
    #pragma unroll 7
    for (int l = l0; l < l0 + 49; l++) {
        float x0 = xz[base + (size_t)l*(2*D_INNER)];
        float acc = bias + w0*xm3 + w1*xm2 + w2*xm1 + w3*x0;
        float sig = 1.f / (1.f + __expf(-acc));
        xb[obase + (size_t)l*D_INNER] = acc * sig;
        xm3 = xm2; xm2 = xm1; xm1 = x0;
    }
}

// ================= scan: chunked register prefetch (CH=7, 196=28*7) =================
#define SCH 7
__global__ __launch_bounds__(128) void scan_kernel(
        const float* __restrict__ xb, const float* __restrict__ xdbl,
        const float* __restrict__ xz, const float* __restrict__ A_log,
        const float* __restrict__ Dskip, const float* __restrict__ dtw,
        const float* __restrict__ dtb, float* __restrict__ y) {
    int b = blockIdx.y;
    int d = blockIdx.x * 128 + threadIdx.x;
    __shared__ float sdbl[L_SEQ][XPROJ_N];
    const float* src = &xdbl[(size_t)b*L_SEQ*XPROJ_N];
    for (int idx = threadIdx.x; idx < L_SEQ*XPROJ_N; idx += 128)
        ((float*)sdbl)[idx] = src[idx];
    __syncthreads();

    float wdt[DT_RANK];
    #pragma unroll
    for (int r = 0; r < DT_RANK; r++) wdt[r] = dtw[d*DT_RANK + r];
    float bdt = dtb[d];
    float a[D_STATE], h[D_STATE];
    #pragma unroll
    for (int n = 0; n < D_STATE; n++) {
        a[n] = -__expf(A_log[d*D_STATE + n]);
        h[n] = 0.f;
    }
    bool structured = true;
    #pragma unroll
    for (int n = 0; n < D_STATE; n++)
        structured = structured && (a[n] == a[0]*(float)(n+1));
    float Dd = Dskip[d];

    size_t base0 = (size_t)b*L_SEQ*D_INNER + d;
    size_t zbase0 = (size_t)b*L_SEQ*(2*D_INNER) + D_INNER + d;

    float ub[2][SCH], zb[2][SCH];
    #pragma unroll
    for (int j = 0; j < SCH; j++) {
        ub[0][j] = xb[base0 + (size_t)j*D_INNER];
        zb[0][j] = xz[zbase0 + (size_t)j*(2*D_INNER)];
    }

    #pragma unroll 2
    for (int c = 0; c < L_SEQ/SCH; c++) {
        int cur = c & 1, nxt = cur ^ 1;
        if (c + 1 < L_SEQ/SCH) {
            int lb = (c + 1) * SCH;
            #pragma unroll
            for (int j = 0; j < SCH; j++) {
                ub[nxt][j] = xb[base0 + (size_t)(lb + j)*D_INNER];
                zb[nxt][j] = xz[zbase0 + (size_t)(lb + j)*(2*D_INNER)];
            }
        }
        #pragma unroll
        for (int j = 0; j < SCH; j++) {
            int l = c * SCH + j;
            float u = ub[cur][j], z = zb[cur][j];
            float dt = bdt;
            #pragma unroll
            for (int r = 0; r < DT_RANK; r++) dt += sdbl[l][r] * wdt[r];
            dt = (dt > 15.f) ? dt : __logf(1.f + __expf(dt));
            float du = dt * u;
            float e[D_STATE];
            if (structured) {
                float w = __expf(dt * a[0]);
                e[0] = w;
                float w2 = w * w;
                e[1] = w2;
                float w4 = w2 * w2;
                e[2] = w2 * w;  e[3] = w4;
                e[4] = w4 * w;  e[5] = w4 * w2;  e[6] = w4 * e[2]; e[7] = w4 * w4;
                #pragma unroll
                for (int n = 8; n < D_STATE; n++) e[n] = e[7] * e[n - 8];
            } else {
                #pragma unroll
                for (int n = 0; n < D_STATE; n++) e[n] = __expf(dt * a[n]);
            }
            float yv = 0.f;
            #pragma unroll
            for (int n = 0; n < D_STATE; n++) {
                h[n] = e[n] * h[n] + du * sdbl[l][DT_RANK + n];
                yv  += h[n] * sdbl[l][DT_RANK + D_STATE + n];
            }
            yv += u * Dd;
            float sig = 1.f / (1.f + __expf(-z));
            y[base0 + (size_t)l*D_INNER] = tf32r(yv * (z * sig));
        }
    }
}

// ================= final =================
__global__ void final_kernel(const float* __restrict__ residual, const float* __restrict__ hidden,
                             const float* __restrict__ nw, const float* __restrict__ nb,
                             const float* __restrict__ hw, const float* __restrict__ hb,
                             float* __restrict__ out) {
    int b = blockIdx.x;
    int t = threadIdx.x;               // 256 threads
    __shared__ float sh[D_MODEL];
    __shared__ float red[8];
    int row = b*L_SEQ + (L_SEQ - 1);
    float v = 0.f;
    if (t < D_MODEL) v = residual[row*D_MODEL + t] + hidden[row*D_MODEL + t];
    float s = v;
    #pragma unroll
    for (int o = 16; o > 0; o >>= 1) s += __shfl_xor_sync(0xffffffffu, s, o);
    if ((t & 31) == 0) red[t >> 5] = s;
    __syncthreads();
    float mean = 0.f;
    #pragma unroll
    for (int i = 0; i < 8; i++) mean += red[i];
    mean *= (1.f/192.f);
    __syncthreads();
    float dv = (t < D_MODEL) ? (v - mean) : 0.f;
    s = dv*dv;
    #pragma unroll
    for (int o = 16; o > 0; o >>= 1) s += __shfl_xor_sync(0xffffffffu, s, o);
    if ((t & 31) == 0) red[t >> 5] = s;
    __syncthreads();
    float var = 0.f;
    #pragma unroll
    for (int i = 0; i < 8; i++) var += red[i];
    var *= (1.f/192.f);
    if (t < D_MODEL) sh[t] = dv * rsqrtf(var + 1e-5f) * nw[t] + nb[t];
    __syncthreads();
    for (int o = t; o < N_CLS; o += 256) {
        float acc = hb[o];
        #pragma unroll 4
        for (int k = 0; k < D_MODEL; k++) acc += sh[k] * hw[o*D_MODEL + k];
        out[b*N_CLS + o] = acc;
    }
}

extern "C" void kernel_launch(void* const* d_in, const int* in_sizes, int n_in,
                              void* d_out, int out_size) {
    const float* x        = (const float*)d_in[0];
    const float* patch_w  = (const float*)d_in[1];
    const float* patch_b  = (const float*)d_in[2];
    const float* in_w     = (const float*)d_in[3];
    const float* conv_w   = (const float*)d_in[4];
    const float* conv_b   = (const float*)d_in[5];
    const float* xproj_w  = (const float*)d_in[6];
    const float* dt_w     = (const float*)d_in[7];
    const float* dt_b     = (const float*)d_in[8];
    const float* A_log    = (const float*)d_in[9];
    const float* D_skip   = (const float*)d_in[10];
    const float* out_w    = (const float*)d_in[11];
    const float* norm_w   = (const float*)d_in[12];
    const float* norm_b   = (const float*)d_in[13];
    const float* normf_w  = (const float*)d_in[14];
    const float* normf_b  = (const float*)d_in[15];
    const float* head_w   = (const float*)d_in[16];
    const float* head_b   = (const float*)d_in[17];
    float* out = (float*)d_out;

    float *hidden, *residual, *hn, *xz, *xb, *xdbl, *y;
    float *wpatch, *win, *wx, *wout;
    cudaGetSymbolAddress((void**)&hidden,   g_hidden);
    cudaGetSymbolAddress((void**)&residual, g_residual);
    cudaGetSymbolAddress((void**)&hn,       g_hn);
    cudaGetSymbolAddress((void**)&xz,       g_xz);
    cudaGetSymbolAddress((void**)&xb,       g_xb);
    cudaGetSymbolAddress((void**)&xdbl,     g_xdbl);
    cudaGetSymbolAddress((void**)&y,        g_y);
    cudaGetSymbolAddress((void**)&wpatch,   g_wpatch);
    cudaGetSymbolAddress((void**)&win,      g_win);
    cudaGetSymbolAddress((void**)&wx,       g_wx);
    cudaGetSymbolAddress((void**)&wout,     g_wout);

    cudaFuncSetAttribute(gemm_mma,  cudaFuncAttributeMaxDynamicSharedMemorySize, 2*STAGE_BYTES);
    cudaFuncSetAttribute(gemm_wide, cudaFuncAttributeMaxDynamicSharedMemorySize, 3*WIDE_STAGE);
    cudaFuncSetAttribute(gemm_mma,  cudaFuncAttributePreferredSharedMemoryCarveout, 100);
    cudaFuncSetAttribute(gemm_wide, cudaFuncAttributePreferredSharedMemoryCarveout, 100);

    // pre-round GEMM weights to tf32
    round_tf32_kernel<<<512, 256>>>(patch_w, wpatch, D_MODEL*K_PATCH);
    round_tf32_kernel<<<2048, 256>>>(in_w,   win,    DEPTH*2*D_INNER*D_MODEL);
    round_tf32_kernel<<<512, 256>>>(xproj_w, wx,     DEPTH*XPROJ_N*D_INNER);
    round_tf32_kernel<<<1024, 256>>>(out_w,  wout,   DEPTH*D_MODEL*D_INNER);

    // patch embed
    im2col_kernel<<<(ROWS*K_PATCH + 255)/256, 256>>>(x, xz);
    gemm_mma<<<dim3(3, ROWS/128), 256, 2*STAGE_BYTES>>>(xz, wpatch, hidden,
                                                        ROWS, D_MODEL, K_PATCH, patch_b);

    for (int i = 0; i < DEPTH; i++) {
        add_ln_kernel<<<ROWS/8, 256>>>(hidden, residual, hn,
                                       norm_w + (size_t)i*D_MODEL, norm_b + (size_t)i*D_MODEL, i == 0);
        gemm_wide<<<dim3(6, ROWS/128), 256, 3*WIDE_STAGE>>>(
            hn, win + (size_t)i*2*D_INNER*D_MODEL, xz, ROWS, 2*D_INNER, D_MODEL);
        conv_silu_kernel<<<dim3(B_SZ, 4), 384>>>(xz, conv_w + (size_t)i*D_INNER*D_CONV,
                                                 conv_b + (size_t)i*D_INNER, xb);
        gemm_mma<<<dim3(1, ROWS/128), 256, 2*STAGE_BYTES>>>(
            xb, wx + (size_t)i*XPROJ_N*D_INNER, xdbl, ROWS, XPROJ_N, D_INNER, nullptr);
        scan_kernel<<<dim3(D_INNER/128, B_SZ), 128>>>(
            xb, xdbl, xz, A_log + (size_t)i*D_INNER*D_STATE, D_skip + (size_t)i*D_INNER,
            dt_w + (size_t)i*D_INNER*DT_RANK, dt_b + (size_t)i*D_INNER, y);
        gemm_mma<<<dim3(3, ROWS/128), 256, 2*STAGE_BYTES>>>(
            y, wout + (size_t)i*D_MODEL*D_INNER, hidden, ROWS, D_MODEL, D_INNER, nullptr);
    }

    final_kernel<<<B_SZ, 256>>>(residual, hidden, normf_w, normf_b, head_w, head_b, out);
}

// round 15
// speedup vs baseline: 1.1134x; 1.0077x over previous
#include <cuda_runtime.h>
#include <math.h>
#include <stdint.h>

#define B_SZ 64
#define L_SEQ 196
#define D_MODEL 192
#define DEPTH 24
#define D_INNER 384
#define D_STATE 16
#define D_CONV 4
#define DT_RANK 12
#define N_CLS 1000
#define XPROJ_N (DT_RANK + 2*D_STATE)   // 44
#define ROWS (B_SZ*L_SEQ)               // 12544
#define K_PATCH 768                      // 3*16*16

// ---------------- scratch ----------------
__device__ float g_residual[ROWS*D_MODEL];
__device__ float g_hn[ROWS*D_MODEL];
__device__ float g_xz[ROWS*2*D_INNER];
__device__ float g_xb[ROWS*D_INNER];
__device__ float g_xdbl[ROWS*XPROJ_N];
__device__ float g_y[ROWS*D_INNER];
__device__ float g_wpatch[D_MODEL*K_PATCH];
__device__ float g_win[DEPTH*2*D_INNER*D_MODEL];
__device__ float g_wx[DEPTH*XPROJ_N*D_INNER];
__device__ float g_wout[DEPTH*D_MODEL*D_INNER];

// ================= helpers =================
__device__ __forceinline__ uint32_t f2tf32(float f) {
    uint32_t o;
    asm("cvt.rna.tf32.f32 %0, %1;" : "=r"(o) : "f"(f));
    return o;
}
__device__ __forceinline__ float tf32r(float f) { return __uint_as_float(f2tf32(f)); }

__global__ void round_tf32_kernel(const float* __restrict__ src, float* __restrict__ dst, int n) {
    int i = blockIdx.x * blockDim.x + threadIdx.x;
    int stride = gridDim.x * blockDim.x;
    for (; i < n; i += stride) dst[i] = tf32r(src[i]);
}

__device__ __forceinline__ uint32_t smem_u32(const void* p) {
    uint32_t a;
    asm("{ .reg .u64 t; cvta.to.shared.u64 t, %1; cvt.u32.u64 %0, t; }" : "=r"(a) : "l"(p));
    return a;
}
#define CP_ASYNC(dst, src, sz) \
    asm volatile("cp.async.cg.shared.global [%0], [%1], 16, %2;" :: "r"(dst), "l"(src), "r"(sz))
#define CP_COMMIT() asm volatile("cp.async.commit_group;" ::: "memory")
#define CP_WAIT(n)  asm volatile("cp.async.wait_group %0;" :: "n"(n) : "memory")

__device__ __forceinline__ void mma1688(float* c, const uint32_t* a, const uint32_t* b) {
    asm volatile(
        "mma.sync.aligned.m16n8k8.row.col.f32.tf32.tf32.f32 "
        "{%0,%1,%2,%3}, {%4,%5,%6,%7}, {%8,%9}, {%0,%1,%2,%3};"
        : "+f"(c[0]), "+f"(c[1]), "+f"(c[2]), "+f"(c[3])
        : "r"(a[0]), "r"(a[1]), "r"(a[2]), "r"(a[3]), "r"(b[0]), "r"(b[1]));
}

#define GA_STRIDE 36

// ================= gemm_mma: BM=128, BN=64, BK=32, single-sync 2-stage =================
// accum!=0: C[m][n] += acc (residual update). bias applied when non-null.
#define STAGE_BYTES ((128+64)*GA_STRIDE*4)   // 27648
#define SMEM_W_OFF (128*GA_STRIDE)

__global__ __launch_bounds__(256, 3) void gemm_mma(
        const float* __restrict__ A, const float* __restrict__ W,
        float* __restrict__ C, int M, int N, int K,
        const float* __restrict__ bias, int accum) {
    extern __shared__ float smem[];
    int tid = threadIdx.x;
    int wid = tid >> 5, lid = tid & 31;
    int wm = wid & 3, wn = wid >> 2;
    int group = lid >> 2, tq = lid & 3;
    int bm = blockIdx.y * 128, bn = blockIdx.x * 64;
    uint32_t sb = smem_u32(smem);
    int nk = K >> 5;

    auto load_stage = [&](int st, int kc) {
        uint32_t base = sb + st * STAGE_BYTES;
        #pragma unroll
        for (int i = 0; i < 4; i++) {
            int q = tid * 4 + i;
            int row = q >> 3, quad = q & 7;
            uint32_t dst = base + (row * GA_STRIDE + quad * 4) * 4;
            const float* src = A + (size_t)(bm + row) * K + (size_t)kc * 32 + quad * 4;
            CP_ASYNC(dst, src, 16);
        }
        #pragma unroll
        for (int i = 0; i < 2; i++) {
            int q = tid * 2 + i;
            int row = q >> 3, quad = q & 7;
            int n = bn + row;
            uint32_t dst = base + (SMEM_W_OFF + row * GA_STRIDE + quad * 4) * 4;
            const float* src = (n < N) ? (W + (size_t)n * K + (size_t)kc * 32 + quad * 4) : W;
            CP_ASYNC(dst, src, (n < N) ? 16 : 0);
        }
        CP_COMMIT();
    };

    float acc[2][4][4] = {};
    load_stage(0, 0);
    for (int k0 = 0; k0 < nk; k0++) {
        CP_WAIT(0);
        __syncthreads();
        if (k0 + 1 < nk) load_stage((k0 + 1) & 1, k0 + 1);
        const float* sA = smem + (size_t)(k0 & 1) * (STAGE_BYTES / 4);
        const float* sW = sA + SMEM_W_OFF;
        #pragma unroll
        for (int kk = 0; kk < 32; kk += 8) {
            uint32_t a[2][4], b[4][2];
            #pragma unroll
            for (int mi = 0; mi < 2; mi++) {
                int r = wm * 32 + mi * 16 + group;
                a[mi][0] = __float_as_uint(sA[r * GA_STRIDE + kk + tq]);
                a[mi][1] = __float_as_uint(sA[(r + 8) * GA_STRIDE + kk + tq]);
                a[mi][2] = __float_as_uint(sA[r * GA_STRIDE + kk + tq + 4]);
                a[mi][3] = __float_as_uint(sA[(r + 8) * GA_STRIDE + kk + tq + 4]);
            }
            #pragma unroll
            for (int ni = 0; ni < 4; ni++) {
                int r = wn * 32 + ni * 8 + group;
                b[ni][0] = __float_as_uint(sW[r * GA_STRIDE + kk + tq]);
                b[ni][1] = __float_as_uint(sW[r * GA_STRIDE + kk + tq + 4]);
            }
            #pragma unroll
            for (int mi = 0; mi < 2; mi++)
                #pragma unroll
                for (int ni = 0; ni < 4; ni++)
                    mma1688(acc[mi][ni], a[mi], b[ni]);
        }
    }
    #pragma unroll
    for (int mi = 0; mi < 2; mi++) {
        int m0 = bm + wm * 32 + mi * 16 + group;
        #pragma unroll
        for (int ni = 0; ni < 4; ni++) {
            int n0 = bn + wn * 32 + ni * 8 + tq * 2;
            if (n0 < N) {
                float bx = 0.f, by = 0.f;
                if (bias) { bx = bias[n0]; by = bias[n0 + 1]; }
                float2 o0 = make_float2(acc[mi][ni][0] + bx, acc[mi][ni][1] + by);
                float2 o1 = make_float2(acc[mi][ni][2] + bx, acc[mi][ni][3] + by);
                float* p0 = &C[(size_t)m0 * N + n0];
                float* p1 = &C[(size_t)(m0 + 8) * N + n0];
                if (accum) {
                    float2 r0 = *(const float2*)p0;
                    float2 r1 = *(const float2*)p1;
                    o0.x = r0.x + o0.x; o0.y = r0.y + o0.y;
                    o1.x = r1.x + o1.x; o1.y = r1.y + o1.y;
                }
                *(float2*)p0 = o0;
                *(float2*)p1 = o1;
            }
        }
    }
}

// ================= gemm_wide: BM=128, BN=128, BK=32, 3-stage single-sync (in_proj) =================
#define WIDE_STAGE ((128+128)*GA_STRIDE*4)   // 36864
#define WIDE_W_OFF (128*GA_STRIDE)

__global__ __launch_bounds__(256, 2) void gemm_wide(
        const float* __restrict__ A, const float* __restrict__ W,
        float* __restrict__ C, int M, int N, int K) {
    extern __shared__ float smem[];
    int tid = threadIdx.x;
    int wid = tid >> 5, lid = tid & 31;
    int wm = wid & 3, wn = wid >> 2;
    int group = lid >> 2, tq = lid & 3;
    int bm = blockIdx.y * 128, bn = blockIdx.x * 128;
    uint32_t sb = smem_u32(smem);
    int nk = K >> 5;

    auto load_stage = [&](int st, int kc) {
        uint32_t base = sb + st * WIDE_STAGE;
        #pragma unroll
        for (int i = 0; i < 4; i++) {
            int q = tid * 4 + i;
            int row = q >> 3, quad = q & 7;
            uint32_t dst = base + (row * GA_STRIDE + quad * 4) * 4;
            const float* src = A + (size_t)(bm + row) * K + (size_t)kc * 32 + quad * 4;
            CP_ASYNC(dst, src, 16);
        }
        #pragma unroll
        for (int i = 0; i < 4; i++) {
            int q = tid * 4 + i;
            int row = q >> 3, quad = q & 7;
            int n = bn + row;
            uint32_t dst = base + (WIDE_W_OFF + row * GA_STRIDE + quad * 4) * 4;
            const float* src = (n < N) ? (W + (size_t)n * K + (size_t)kc * 32 + quad * 4) : W;
            CP_ASYNC(dst, src, (n < N) ? 16 : 0);
        }
        CP_COMMIT();
    };

    float acc[2][8][4] = {};
    load_stage(0, 0);
    load_stage(1, 1);
    for (int k0 = 0; k0 < nk; k0++) {
        if (k0 < nk - 1) CP_WAIT(1);
        else             CP_WAIT(0);
        __syncthreads();
        if (k0 + 2 < nk) load_stage((k0 + 2) % 3, k0 + 2);
        const float* sA = smem + (size_t)(k0 % 3) * (WIDE_STAGE / 4);
        const float* sW = sA + WIDE_W_OFF;
        #pragma unroll
        for (int kk = 0; kk < 32; kk += 8) {
            uint32_t a[2][4], b[8][2];
            #pragma unroll
            for (int mi = 0; mi < 2; mi++) {
                int r = wm * 32 + mi * 16 + group;
                a[mi][0] = __float_as_uint(sA[r * GA_STRIDE + kk + tq]);
                a[mi][1] = __float_as_uint(sA[(r + 8) * GA_STRIDE + kk + tq]);
                a[mi][2] = __float_as_uint(sA[r * GA_STRIDE + kk + tq + 4]);
                a[mi][3] = __float_as_uint(sA[(r + 8) * GA_STRIDE + kk + tq + 4]);
            }
            #pragma unroll
            for (int ni = 0; ni < 8; ni++) {
                int r = wn * 64 + ni * 8 + group;
                b[ni][0] = __float_as_uint(sW[r * GA_STRIDE + kk + tq]);
                b[ni][1] = __float_as_uint(sW[r * GA_STRIDE + kk + tq + 4]);
            }
            #pragma unroll
            for (int mi = 0; mi < 2; mi++)
                #pragma unroll
                for (int ni = 0; ni < 8; ni++)
                    mma1688(acc[mi][ni], a[mi], b[ni]);
        }
    }
    #pragma unroll
    for (int mi = 0; mi < 2; mi++) {
        int m0 = bm + wm * 32 + mi * 16 + group;
        #pragma unroll
        for (int ni = 0; ni < 8; ni++) {
            int n0 = bn + wn * 64 + ni * 8 + tq * 2;
            if (n0 < N) {
                *(float2*)&C[(size_t)m0 * N + n0] = make_float2(acc[mi][ni][0], acc[mi][ni][1]);
                *(float2*)&C[(size_t)(m0 + 8) * N + n0] = make_float2(acc[mi][ni][2], acc[mi][ni][3]);
            }
        }
    }
}

// ================= im2col =================
__global__ void im2col_kernel(const float* __restrict__ x, float* __restrict__ col) {
    int idx = blockIdx.x * blockDim.x + threadIdx.x;
    if (idx >= ROWS * K_PATCH) return;
    int k  = idx % K_PATCH;
    int bl = idx / K_PATCH;
    int l  = bl % L_SEQ;
    int b  = bl / L_SEQ;
    int c  = k / 256;
    int rem = k % 256;
    int i = rem / 16, j = rem % 16;
    int ph = l / 14, pw = l % 14;
    col[idx] = tf32r(x[((b*3 + c)*224 + ph*16 + i)*224 + pw*16 + j]);
}

// ================= warp-per-row pure LayerNorm: residual -> hn =================
__global__ __launch_bounds__(256) void ln_kernel(
        const float* __restrict__ residual, float* __restrict__ hn,
        const float* __restrict__ w, const float* __restrict__ b) {
    int warp = threadIdx.x >> 5, lane = threadIdx.x & 31;
    int row = blockIdx.x * 8 + warp;
    size_t base = (size_t)row * D_MODEL;
    float v[6];
    float sum = 0.f;
    #pragma unroll
    for (int j = 0; j < 6; j++) {
        v[j] = residual[base + lane + j*32];
        sum += v[j];
    }
    #pragma unroll
    for (int o = 16; o > 0; o >>= 1) sum += __shfl_xor_sync(0xffffffffu, sum, o);
    float mean = sum * (1.f/192.f);
    float sq = 0.f;
    #pragma unroll
    for (int j = 0; j < 6; j++) { float d = v[j] - mean; sq += d*d; }
    #pragma unroll
    for (int o = 16; o > 0; o >>= 1) sq += __shfl_xor_sync(0xffffffffu, sq, o);
    float rstd = rsqrtf(sq * (1.f/192.f) + 1e-5f);
    #pragma unroll
    for (int j = 0; j < 6; j++) {
        int c = lane + j*32;
        hn[base + c] = tf32r((v[j] - mean) * rstd * w[c] + b[c]);
    }
}

// ================= causal depthwise conv1d + SiLU, sliding window =================
__global__ __launch_bounds__(384) void conv_silu_kernel(
        const float* __restrict__ xz, const float* __restrict__ cw,
        const float* __restrict__ cb, float* __restrict__ xb) {
    int d = threadIdx.x;
    int b = blockIdx.x;
    int l0 = blockIdx.y * 49;
    float w0 = cw[d*D_CONV+0], w1 = cw[d*D_CONV+1], w2 = cw[d*D_CONV+2], w3 = cw[d*D_CONV+3];
    float bias = cb[d];
    size_t base = (size_t)b*L_SEQ*(2*D_INNER) + d;
    size_t obase = (size_t)b*L_SEQ*D_INNER + d;
    float xm3 = (l0 >= 3) ? xz[base + (size_t)(l0-3)*(2*D_INNER)] : 0.f;
    float xm2 = (l0 >= 2) ? xz[base + (size_t)(l0-2)*(2*D_INNER)] : 0.f;
    float xm1 = (l0 >= 1) ? xz[base + (size_t)(l0-1)*(2*D_INNER)] : 0.f;
    #pragma unroll 7
    for (int l = l0; l < l0 + 49; l++) {
        float x0 = xz[base + (size_t)l*(2*D_INNER)];
        float acc = bias + w0*xm3 + w1*xm2 + w2*xm1 + w3*x0;
        float sig = 1.f / (1.f + __expf(-acc));
        xb[obase + (size_t)l*D_INNER] = acc * sig;
        xm3 = xm2; xm2 = xm1; xm1 = x0;
    }
}

// ================= scan: chunked prefetch + tree reductions =================
#define SCH 7
__global__ __launch_bounds__(128) void scan_kernel(
        const float* __restrict__ xb, const float* __restrict__ xdbl,
        const float* __restrict__ xz, const float* __restrict__ A_log,
        const float* __restrict__ Dskip, const float* __restrict__ dtw,
        const float* __restrict__ dtb, float* __restrict__ y) {
    int b = blockIdx.y;
    int d = blockIdx.x * 128 + threadIdx.x;
    __shared__ float sdbl[L_SEQ][XPROJ_N];
    const float* src = &xdbl[(size_t)b*L_SEQ*XPROJ_N];
    for (int idx = threadIdx.x; idx < L_SEQ*XPROJ_N; idx += 128)
        ((float*)sdbl)[idx] = src[idx];
    __syncthreads();

    float wdt[DT_RANK];
    #pragma unroll
    for (int r = 0; r < DT_RANK; r++) wdt[r] = dtw[d*DT_RANK + r];
    float bdt = dtb[d];
    float a[D_STATE], h[D_STATE];
    #pragma unroll
    for (int n = 0; n < D_STATE; n++) {
        a[n] = -__expf(A_log[d*D_STATE + n]);
        h[n] = 0.f;
    }
    bool structured = true;
    #pragma unroll
    for (int n = 0; n < D_STATE; n++)
        structured = structured && (a[n] == a[0]*(float)(n+1));
    float Dd = Dskip[d];

    size_t base0 = (size_t)b*L_SEQ*D_INNER + d;
    size_t zbase0 = (size_t)b*L_SEQ*(2*D_INNER) + D_INNER + d;

    float ub[2][SCH], zb[2][SCH];
    #pragma unroll
    for (int j = 0; j < SCH; j++) {
        ub[0][j] = xb[base0 + (size_t)j*D_INNER];
        zb[0][j] = xz[zbase0 + (size_t)j*(2*D_INNER)];
    }

    #pragma unroll 2
    for (int c = 0; c < L_SEQ/SCH; c++) {
        int cur = c & 1, nxt = cur ^ 1;
        if (c + 1 < L_SEQ/SCH) {
            int lb = (c + 1) * SCH;
            #pragma unroll
            for (int j = 0; j < SCH; j++) {
                ub[nxt][j] = xb[base0 + (size_t)(lb + j)*D_INNER];
                zb[nxt][j] = xz[zbase0 + (size_t)(lb + j)*(2*D_INNER)];
            }
        }
        #pragma unroll
        for (int j = 0; j < SCH; j++) {
            int l = c * SCH + j;
            float u = ub[cur][j], z = zb[cur][j];
            // dt projection: two interleaved partial sums (tree) + bias
            float dt0 = bdt, dt1 = 0.f;
            #pragma unroll
            for (int r = 0; r < DT_RANK; r += 2) {
                dt0 += sdbl[l][r]   * wdt[r];
                dt1 += sdbl[l][r+1] * wdt[r+1];
            }
            float dt = dt0 + dt1;
            dt = (dt > 15.f) ? dt : __logf(1.f + __expf(dt));
            float du = dt * u;
            float e[D_STATE];
            if (structured) {
                float w = __expf(dt * a[0]);
                e[0] = w;
                float w2 = w * w;
                e[1] = w2;
                float w4 = w2 * w2;
                e[2] = w2 * w;  e[3] = w4;
                e[4] = w4 * w;  e[5] = w4 * w2;  e[6] = w4 * e[2]; e[7] = w4 * w4;
                #pragma unroll
                for (int n = 8; n < D_STATE; n++) e[n] = e[7] * e[n - 8];
            } else {
                #pragma unroll
                for (int n = 0; n < D_STATE; n++) e[n] = __expf(dt * a[n]);
            }
            // state update + output: 4 partial accumulators (tree)
            float yv0 = 0.f, yv1 = 0.f, yv2 = 0.f, yv3 = 0.f;
            #pragma unroll
            for (int n = 0; n < D_STATE; n += 4) {
                h[n]   = e[n]   * h[n]   + du * sdbl[l][DT_RANK + n];
                h[n+1] = e[n+1] * h[n+1] + du * sdbl[l][DT_RANK + n+1];
                h[n+2] = e[n+2] * h[n+2] + du * sdbl[l][DT_RANK + n+2];
                h[n+3] = e[n+3] * h[n+3] + du * sdbl[l][DT_RANK + n+3];
                yv0 += h[n]   * sdbl[l][DT_RANK + D_STATE + n];
                yv1 += h[n+1] * sdbl[l][DT_RANK + D_STATE + n+1];
                yv2 += h[n+2] * sdbl[l][DT_RANK + D_STATE + n+2];
                yv3 += h[n+3] * sdbl[l][DT_RANK + D_STATE + n+3];
            }
            float yv = (yv0 + yv1) + (yv2 + yv3) + u * Dd;
            float sig = 1.f / (1.f + __expf(-z));
            y[base0 + (size_t)l*D_INNER] = tf32r(yv * (z * sig));
        }
    }
}

// ================= final: LN(residual last token) + head =================
__global__ void final_kernel(const float* __restrict__ residual,
                             const float* __restrict__ nw, const float* __restrict__ nb,
                             const float* __restrict__ hw, const float* __restrict__ hb,
                             float* __restrict__ out) {
    int b = blockIdx.x;
    int t = threadIdx.x;               // 256 threads
    __shared__ float sh[D_MODEL];
    __shared__ float red[8];
    int row = b*L_SEQ + (L_SEQ - 1);
    float v = 0.f;
    if (t < D_MODEL) v = residual[row*D_MODEL + t];
    float s = v;
    #pragma unroll
    for (int o = 16; o > 0; o >>= 1) s += __shfl_xor_sync(0xffffffffu, s, o);
    if ((t & 31) == 0) red[t >> 5] = s;
    __syncthreads();
    float mean = 0.f;
    #pragma unroll
    for (int i = 0; i < 8; i++) mean += red[i];
    mean *= (1.f/192.f);
    __syncthreads();
    float dv = (t < D_MODEL) ? (v - mean) : 0.f;
    s = dv*dv;
    #pragma unroll
    for (int o = 16; o > 0; o >>= 1) s += __shfl_xor_sync(0xffffffffu, s, o);
    if ((t & 31) == 0) red[t >> 5] = s;
    __syncthreads();
    float var = 0.f;
    #pragma unroll
    for (int i = 0; i < 8; i++) var += red[i];
    var *= (1.f/192.f);
    if (t < D_MODEL) sh[t] = dv * rsqrtf(var + 1e-5f) * nw[t] + nb[t];
    __syncthreads();
    for (int o = t; o < N_CLS; o += 256) {
        float acc = hb[o];
        #pragma unroll 4
        for (int k = 0; k < D_MODEL; k++) acc += sh[k] * hw[o*D_MODEL + k];
        out[b*N_CLS + o] = acc;
    }
}

extern "C" void kernel_launch(void* const* d_in, const int* in_sizes, int n_in,
                              void* d_out, int out_size) {
    const float* x        = (const float*)d_in[0];
    const float* patch_w  = (const float*)d_in[1];
    const float* patch_b  = (const float*)d_in[2];
    const float* in_w     = (const float*)d_in[3];
    const float* conv_w   = (const float*)d_in[4];
    const float* conv_b   = (const float*)d_in[5];
    const float* xproj_w  = (const float*)d_in[6];
    const float* dt_w     = (const float*)d_in[7];
    const float* dt_b     = (const float*)d_in[8];
    const float* A_log    = (const float*)d_in[9];
    const float* D_skip   = (const float*)d_in[10];
    const float* out_w    = (const float*)d_in[11];
    const float* norm_w   = (const float*)d_in[12];
    const float* norm_b   = (const float*)d_in[13];
    const float* normf_w  = (const float*)d_in[14];
    const float* normf_b  = (const float*)d_in[15];
    const float* head_w   = (const float*)d_in[16];
    const float* head_b   = (const float*)d_in[17];
    float* out = (float*)d_out;

    float *residual, *hn, *xz, *xb, *xdbl, *y;
    float *wpatch, *win, *wx, *wout;
    cudaGetSymbolAddress((void**)&residual, g_residual);
    cudaGetSymbolAddress((void**)&hn,       g_hn);
    cudaGetSymbolAddress((void**)&xz,       g_xz);
    cudaGetSymbolAddress((void**)&xb,       g_xb);
    cudaGetSymbolAddress((void**)&xdbl,     g_xdbl);
    cudaGetSymbolAddress((void**)&y,        g_y);
    cudaGetSymbolAddress((void**)&wpatch,   g_wpatch);
    cudaGetSymbolAddress((void**)&win,      g_win);
    cudaGetSymbolAddress((void**)&wx,       g_wx);
    cudaGetSymbolAddress((void**)&wout,     g_wout);

    cudaFuncSetAttribute(gemm_mma,  cudaFuncAttributeMaxDynamicSharedMemorySize, 2*STAGE_BYTES);
    cudaFuncSetAttribute(gemm_wide, cudaFuncAttributeMaxDynamicSharedMemorySize, 3*WIDE_STAGE);
    cudaFuncSetAttribute(gemm_mma,  cudaFuncAttributePreferredSharedMemoryCarveout, 100);
    cudaFuncSetAttribute(gemm_wide, cudaFuncAttributePreferredSharedMemoryCarveout, 100);

    // pre-round GEMM weights to tf32
    round_tf32_kernel<<<512, 256>>>(patch_w, wpatch, D_MODEL*K_PATCH);
    round_tf32_kernel<<<2048, 256>>>(in_w,   win,    DEPTH*2*D_INNER*D_MODEL);
    round_tf32_kernel<<<512, 256>>>(xproj_w, wx,     DEPTH*XPROJ_N*D_INNER);
    round_tf32_kernel<<<1024, 256>>>(out_w,  wout,   DEPTH*D_MODEL*D_INNER);

    // patch embed -> residual (plain write)
    im2col_kernel<<<(ROWS*K_PATCH + 255)/256, 256>>>(x, xz);
    gemm_mma<<<dim3(3, ROWS/128), 256, 2*STAGE_BYTES>>>(xz, wpatch, residual,
                                                        ROWS, D_MODEL, K_PATCH, patch_b, 0);

    for (int i = 0; i < DEPTH; i++) {
        ln_kernel<<<ROWS/8, 256>>>(residual, hn,
                                   norm_w + (size_t)i*D_MODEL, norm_b + (size_t)i*D_MODEL);
        gemm_wide<<<dim3(6, ROWS/128), 256, 3*WIDE_STAGE>>>(
            hn, win + (size_t)i*2*D_INNER*D_MODEL, xz, ROWS, 2*D_INNER, D_MODEL);
        conv_silu_kernel<<<dim3(B_SZ, 4), 384>>>(xz, conv_w + (size_t)i*D_INNER*D_CONV,
                                                 conv_b + (size_t)i*D_INNER, xb);
        gemm_mma<<<dim3(1, ROWS/128), 256, 2*STAGE_BYTES>>>(
            xb, wx + (size_t)i*XPROJ_N*D_INNER, xdbl, ROWS, XPROJ_N, D_INNER, nullptr, 0);
        scan_kernel<<<dim3(D_INNER/128, B_SZ), 128>>>(
            xb, xdbl, xz, A_log + (size_t)i*D_INNER*D_STATE, D_skip + (size_t)i*D_INNER,
            dt_w + (size_t)i*D_INNER*DT_RANK, dt_b + (size_t)i*D_INNER, y);
        gemm_mma<<<dim3(3, ROWS/128), 256, 2*STAGE_BYTES>>>(
            y, wout + (size_t)i*D_MODEL*D_INNER, residual, ROWS, D_MODEL, D_INNER, nullptr, 1);
    }

    final_kernel<<<B_SZ, 256>>>(residual, normf_w, normf_b, head_w, head_b, out);
}

// round 16
// speedup vs baseline: 1.1165x; 1.0027x over previous
#include <cuda_runtime.h>
#include <math.h>
#include <stdint.h>

#define B_SZ 64
#define L_SEQ 196
#define D_MODEL 192
#define DEPTH 24
#define D_INNER 384
#define D_STATE 16
#define D_CONV 4
#define DT_RANK 12
#define N_CLS 1000
#define XPROJ_N (DT_RANK + 2*D_STATE)   // 44
#define ROWS (B_SZ*L_SEQ)               // 12544
#define K_PATCH 768                      // 3*16*16

// ---------------- scratch ----------------
__device__ float g_residual[ROWS*D_MODEL];
__device__ float g_hn[ROWS*D_MODEL];
__device__ float g_xz[ROWS*2*D_INNER];
__device__ float g_xb[ROWS*D_INNER];
__device__ float g_xdbl[2*ROWS*XPROJ_N];    // two split-K halves
__device__ float g_y[ROWS*D_INNER];
__device__ float g_wpatch[D_MODEL*K_PATCH];
__device__ float g_win[DEPTH*2*D_INNER*D_MODEL];
__device__ float g_wx[DEPTH*XPROJ_N*D_INNER];
__device__ float g_wout[DEPTH*D_MODEL*D_INNER];

// ================= helpers =================
__device__ __forceinline__ uint32_t f2tf32(float f) {
    uint32_t o;
    asm("cvt.rna.tf32.f32 %0, %1;" : "=r"(o) : "f"(f));
    return o;
}
__device__ __forceinline__ float tf32r(float f) { return __uint_as_float(f2tf32(f)); }

__global__ void round_tf32_kernel(const float* __restrict__ src, float* __restrict__ dst, int n) {
    int i = blockIdx.x * blockDim.x + threadIdx.x;
    int stride = gridDim.x * blockDim.x;
    for (; i < n; i += stride) dst[i] = tf32r(src[i]);
}

__device__ __forceinline__ uint32_t smem_u32(const void* p) {
    uint32_t a;
    asm("{ .reg .u64 t; cvta.to.shared.u64 t, %1; cvt.u32.u64 %0, t; }" : "=r"(a) : "l"(p));
    return a;
}
#define CP_ASYNC(dst, src, sz) \
    asm volatile("cp.async.cg.shared.global [%0], [%1], 16, %2;" :: "r"(dst), "l"(src), "r"(sz))
#define CP_COMMIT() asm volatile("cp.async.commit_group;" ::: "memory")
#define CP_WAIT(n)  asm volatile("cp.async.wait_group %0;" :: "n"(n) : "memory")

__device__ __forceinline__ void mma1688(float* c, const uint32_t* a, const uint32_t* b) {
    asm volatile(
        "mma.sync.aligned.m16n8k8.row.col.f32.tf32.tf32.f32 "
        "{%0,%1,%2,%3}, {%4,%5,%6,%7}, {%8,%9}, {%0,%1,%2,%3};"
        : "+f"(c[0]), "+f"(c[1]), "+f"(c[2]), "+f"(c[3])
        : "r"(a[0]), "r"(a[1]), "r"(a[2]), "r"(a[3]), "r"(b[0]), "r"(b[1]));
}

#define GA_STRIDE 36

// ================= gemm_mma: BM=128, BN=64, BK=32, single-sync 2-stage =================
// blockIdx.z selects a K-split slice when kslices>1 (A/W offset z*Kslice, C offset z*Cstride).
#define STAGE_BYTES ((128+64)*GA_STRIDE*4)   // 27648
#define SMEM_W_OFF (128*GA_STRIDE)

__global__ __launch_bounds__(256, 3) void gemm_mma(
        const float* __restrict__ A, const float* __restrict__ W,
        float* __restrict__ C, int M, int N, int K,
        const float* __restrict__ bias, int accum,
        int Kfull, size_t Cstride) {
    extern __shared__ float smem[];
    int tid = threadIdx.x;
    int wid = tid >> 5, lid = tid & 31;
    int wm = wid & 3, wn = wid >> 2;
    int group = lid >> 2, tq = lid & 3;
    int bm = blockIdx.y * 128, bn = blockIdx.x * 64;
    int kofs = blockIdx.z * K;            // K = slice size; Kfull = row pitch
    C += (size_t)blockIdx.z * Cstride;
    uint32_t sb = smem_u32(smem);
    int nk = K >> 5;

    auto load_stage = [&](int st, int kc) {
        uint32_t base = sb + st * STAGE_BYTES;
        #pragma unroll
        for (int i = 0; i < 4; i++) {
            int q = tid * 4 + i;
            int row = q >> 3, quad = q & 7;
            uint32_t dst = base + (row * GA_STRIDE + quad * 4) * 4;
            const float* src = A + (size_t)(bm + row) * Kfull + kofs + (size_t)kc * 32 + quad * 4;
            CP_ASYNC(dst, src, 16);
        }
        #pragma unroll
        for (int i = 0; i < 2; i++) {
            int q = tid * 2 + i;
            int row = q >> 3, quad = q & 7;
            int n = bn + row;
            uint32_t dst = base + (SMEM_W_OFF + row * GA_STRIDE + quad * 4) * 4;
            const float* src = (n < N) ? (W + (size_t)n * Kfull + kofs + (size_t)kc * 32 + quad * 4) : W;
            CP_ASYNC(dst, src, (n < N) ? 16 : 0);
        }
        CP_COMMIT();
    };

    float acc[2][4][4] = {};
    load_stage(0, 0);
    for (int k0 = 0; k0 < nk; k0++) {
        CP_WAIT(0);
        __syncthreads();
        if (k0 + 1 < nk) load_stage((k0 + 1) & 1, k0 + 1);
        const float* sA = smem + (size_t)(k0 & 1) * (STAGE_BYTES / 4);
        const float* sW = sA + SMEM_W_OFF;
        #pragma unroll
        for (int kk = 0; kk < 32; kk += 8) {
            uint32_t a[2][4], b[4][2];
            #pragma unroll
            for (int mi = 0; mi < 2; mi++) {
                int r = wm * 32 + mi * 16 + group;
                a[mi][0] = __float_as_uint(sA[r * GA_STRIDE + kk + tq]);
                a[mi][1] = __float_as_uint(sA[(r + 8) * GA_STRIDE + kk + tq]);
                a[mi][2] = __float_as_uint(sA[r * GA_STRIDE + kk + tq + 4]);
                a[mi][3] = __float_as_uint(sA[(r + 8) * GA_STRIDE + kk + tq + 4]);
            }
            #pragma unroll
            for (int ni = 0; ni < 4; ni++) {
                int r = wn * 32 + ni * 8 + group;
                b[ni][0] = __float_as_uint(sW[r * GA_STRIDE + kk + tq]);
                b[ni][1] = __float_as_uint(sW[r * GA_STRIDE + kk + tq + 4]);
            }
            #pragma unroll
            for (int mi = 0; mi < 2; mi++)
                #pragma unroll
                for (int ni = 0; ni < 4; ni++)
                    mma1688(acc[mi][ni], a[mi], b[ni]);
        }
    }
    #pragma unroll
    for (int mi = 0; mi < 2; mi++) {
        int m0 = bm + wm * 32 + mi * 16 + group;
        #pragma unroll
        for (int ni = 0; ni < 4; ni++) {
            int n0 = bn + wn * 32 + ni * 8 + tq * 2;
            if (n0 < N) {
                float bx = 0.f, by = 0.f;
                if (bias) { bx = bias[n0]; by = bias[n0 + 1]; }
                float2 o0 = make_float2(acc[mi][ni][0] + bx, acc[mi][ni][1] + by);
                float2 o1 = make_float2(acc[mi][ni][2] + bx, acc[mi][ni][3] + by);
                float* p0 = &C[(size_t)m0 * N + n0];
                float* p1 = &C[(size_t)(m0 + 8) * N + n0];
                if (accum) {
                    float2 r0 = *(const float2*)p0;
                    float2 r1 = *(const float2*)p1;
                    o0.x = r0.x + o0.x; o0.y = r0.y + o0.y;
                    o1.x = r1.x + o1.x; o1.y = r1.y + o1.y;
                }
                *(float2*)p0 = o0;
                *(float2*)p1 = o1;
            }
        }
    }
}

// ================= gemm_wide: BM=128, BN=128, BK=32, 3-stage single-sync (in_proj) =================
#define WIDE_STAGE ((128+128)*GA_STRIDE*4)   // 36864
#define WIDE_W_OFF (128*GA_STRIDE)

__global__ __launch_bounds__(256, 2) void gemm_wide(
        const float* __restrict__ A, const float* __restrict__ W,
        float* __restrict__ C, int M, int N, int K) {
    extern __shared__ float smem[];
    int tid = threadIdx.x;
    int wid = tid >> 5, lid = tid & 31;
    int wm = wid & 3, wn = wid >> 2;
    int group = lid >> 2, tq = lid & 3;
    int bm = blockIdx.y * 128, bn = blockIdx.x * 128;
    uint32_t sb = smem_u32(smem);
    int nk = K >> 5;

    auto load_stage = [&](int st, int kc) {
        uint32_t base = sb + st * WIDE_STAGE;
        #pragma unroll
        for (int i = 0; i < 4; i++) {
            int q = tid * 4 + i;
            int row = q >> 3, quad = q & 7;
            uint32_t dst = base + (row * GA_STRIDE + quad * 4) * 4;
            const float* src = A + (size_t)(bm + row) * K + (size_t)kc * 32 + quad * 4;
            CP_ASYNC(dst, src, 16);
        }
        #pragma unroll
        for (int i = 0; i < 4; i++) {
            int q = tid * 4 + i;
            int row = q >> 3, quad = q & 7;
            int n = bn + row;
            uint32_t dst = base + (WIDE_W_OFF + row * GA_STRIDE + quad * 4) * 4;
            const float* src = (n < N) ? (W + (size_t)n * K + (size_t)kc * 32 + quad * 4) : W;
            CP_ASYNC(dst, src, (n < N) ? 16 : 0);
        }
        CP_COMMIT();
    };

    float acc[2][8][4] = {};
    load_stage(0, 0);
    load_stage(1, 1);
    for (int k0 = 0; k0 < nk; k0++) {
        if (k0 < nk - 1) CP_WAIT(1);
        else             CP_WAIT(0);
        __syncthreads();
        if (k0 + 2 < nk) load_stage((k0 + 2) % 3, k0 + 2);
        const float* sA = smem + (size_t)(k0 % 3) * (WIDE_STAGE / 4);
        const float* sW = sA + WIDE_W_OFF;
        #pragma unroll
        for (int kk = 0; kk < 32; kk += 8) {
            uint32_t a[2][4], b[8][2];
            #pragma unroll
            for (int mi = 0; mi < 2; mi++) {
                int r = wm * 32 + mi * 16 + group;
                a[mi][0] = __float_as_uint(sA[r * GA_STRIDE + kk + tq]);
                a[mi][1] = __float_as_uint(sA[(r + 8) * GA_STRIDE + kk + tq]);
                a[mi][2] = __float_as_uint(sA[r * GA_STRIDE + kk + tq + 4]);
                a[mi][3] = __float_as_uint(sA[(r + 8) * GA_STRIDE + kk + tq + 4]);
            }
            #pragma unroll
            for (int ni = 0; ni < 8; ni++) {
                int r = wn * 64 + ni * 8 + group;
                b[ni][0] = __float_as_uint(sW[r * GA_STRIDE + kk + tq]);
                b[ni][1] = __float_as_uint(sW[r * GA_STRIDE + kk + tq + 4]);
            }
            #pragma unroll
            for (int mi = 0; mi < 2; mi++)
                #pragma unroll
                for (int ni = 0; ni < 8; ni++)
                    mma1688(acc[mi][ni], a[mi], b[ni]);
        }
    }
    #pragma unroll
    for (int mi = 0; mi < 2; mi++) {
        int m0 = bm + wm * 32 + mi * 16 + group;
        #pragma unroll
        for (int ni = 0; ni < 8; ni++) {
            int n0 = bn + wn * 64 + ni * 8 + tq * 2;
            if (n0 < N) {
                *(float2*)&C[(size_t)m0 * N + n0] = make_float2(acc[mi][ni][0], acc[mi][ni][1]);
                *(float2*)&C[(size_t)(m0 + 8) * N + n0] = make_float2(acc[mi][ni][2], acc[mi][ni][3]);
            }
        }
    }
}

// ================= im2col =================
__global__ void im2col_kernel(const float* __restrict__ x, float* __restrict__ col) {
    int idx = blockIdx.x * blockDim.x + threadIdx.x;
    if (idx >= ROWS * K_PATCH) return;
    int k  = idx % K_PATCH;
    int bl = idx / K_PATCH;
    int l  = bl % L_SEQ;
    int b  = bl / L_SEQ;
    int c  = k / 256;
    int rem = k % 256;
    int i = rem / 16, j = rem % 16;
    int ph = l / 14, pw = l % 14;
    col[idx] = tf32r(x[((b*3 + c)*224 + ph*16 + i)*224 + pw*16 + j]);
}

// ================= warp-per-row pure LayerNorm: residual -> hn =================
__global__ __launch_bounds__(256) void ln_kernel(
        const float* __restrict__ residual, float* __restrict__ hn,
        const float* __restrict__ w, const float* __restrict__ b) {
    int warp = threadIdx.x >> 5, lane = threadIdx.x & 31;
    int row = blockIdx.x * 8 + warp;
    size_t base = (size_t)row * D_MODEL;
    float v[6];
    float sum = 0.f;
    #pragma unroll
    for (int j = 0; j < 6; j++) {
        v[j] = residual[base + lane + j*32];
        sum += v[j];
    }
    #pragma unroll
    for (int o = 16; o > 0; o >>= 1) sum += __shfl_xor_sync(0xffffffffu, sum, o);
    float mean = sum * (1.f/192.f);
    float sq = 0.f;
    #pragma unroll
    for (int j = 0; j < 6; j++) { float d = v[j] - mean; sq += d*d; }
    #pragma unroll
    for (int o = 16; o > 0; o >>= 1) sq += __shfl_xor_sync(0xffffffffu, sq, o);
    float rstd = rsqrtf(sq * (1.f/192.f) + 1e-5f);
    #pragma unroll
    for (int j = 0; j < 6; j++) {
        int c = lane + j*32;
        hn[base + c] = tf32r((v[j] - mean) * rstd * w[c] + b[c]);
    }
}

// ================= causal depthwise conv1d + SiLU, sliding window =================
__global__ __launch_bounds__(384) void conv_silu_kernel(
        const float* __restrict__ xz, const float* __restrict__ cw,
        const float* __restrict__ cb, float* __restrict__ xb) {
    int d = threadIdx.x;
    int b = blockIdx.x;
    int l0 = blockIdx.y * 49;
    float w0 = cw[d*D_CONV+0], w1 = cw[d*D_CONV+1], w2 = cw[d*D_CONV+2], w3 = cw[d*D_CONV+3];
    float bias = cb[d];
    size_t base = (size_t)b*L_SEQ*(2*D_INNER) + d;
    size_t obase = (size_t)b*L_SEQ*D_INNER + d;
    float xm3 = (l0 >= 3) ? xz[base + (size_t)(l0-3)*(2*D_INNER)] : 0.f;
    float xm2 = (l0 >= 2) ? xz[base + (size_t)(l0-2)*(2*D_INNER)] : 0.f;
    float xm1 = (l0 >= 1) ? xz[base + (size_t)(l0-1)*(2*D_INNER)] : 0.f;
    #pragma unroll 7
    for (int l = l0; l < l0 + 49; l++) {
        float x0 = xz[base + (size_t)l*(2*D_INNER)];
        float acc = bias + w0*xm3 + w1*xm2 + w2*xm1 + w3*x0;
        float sig = 1.f / (1.f + __expf(-acc));
        xb[obase + (size_t)l*D_INNER] = acc * sig;
        xm3 = xm2; xm2 = xm1; xm1 = x0;
    }
}

// ================= scan: 2 threads per channel, chunked prefetch =================
// block 256 = 128 channels x 2 halves. Each thread owns 8 of 16 states.
#define SCH 7
__global__ __launch_bounds__(256) void scan_kernel(
        const float* __restrict__ xb, const float* __restrict__ xdbl,
        const float* __restrict__ xz, const float* __restrict__ A_log,
        const float* __restrict__ Dskip, const float* __restrict__ dtw,
        const float* __restrict__ dtb, float* __restrict__ y) {
    int b = blockIdx.y;
    int t = threadIdx.x;
    int dl = t >> 1;                  // channel within block
    int half = t & 1;                 // state group: [half*8, half*8+8)
    int d = blockIdx.x * 128 + dl;
    __shared__ float sdbl[L_SEQ][XPROJ_N];
    {   // sum the two split-K halves of xdbl
        const float* s0 = &xdbl[(size_t)b*L_SEQ*XPROJ_N];
        const float* s1 = s0 + (size_t)ROWS*XPROJ_N;
        for (int idx = t; idx < L_SEQ*XPROJ_N; idx += 256)
            ((float*)sdbl)[idx] = s0[idx] + s1[idx];
    }
    __syncthreads();

    float wdt[DT_RANK];
    #pragma unroll
    for (int r = 0; r < DT_RANK; r++) wdt[r] = dtw[d*DT_RANK + r];
    float bdt = dtb[d];
    float a0 = -__expf(A_log[d*D_STATE]);
    float a[8], h[8];
    #pragma unroll
    for (int n = 0; n < 8; n++) {
        a[n] = -__expf(A_log[d*D_STATE + half*8 + n]);
        h[n] = 0.f;
    }
    bool structured = true;
    #pragma unroll
    for (int n = 0; n < 8; n++)
        structured = structured && (a[n] == a0*(float)(half*8 + n + 1));
    float Dd = Dskip[d];

    size_t base0 = (size_t)b*L_SEQ*D_INNER + d;
    size_t zbase0 = (size_t)b*L_SEQ*(2*D_INNER) + D_INNER + d;

    float ub[2][SCH], zb[2][SCH];
    #pragma unroll
    for (int j = 0; j < SCH; j++) {
        ub[0][j] = xb[base0 + (size_t)j*D_INNER];
        zb[0][j] = xz[zbase0 + (size_t)j*(2*D_INNER)];
    }

    #pragma unroll 2
    for (int c = 0; c < L_SEQ/SCH; c++) {
        int cur = c & 1, nxt = cur ^ 1;
        if (c + 1 < L_SEQ/SCH) {
            int lb = (c + 1) * SCH;
            #pragma unroll
            for (int j = 0; j < SCH; j++) {
                ub[nxt][j] = xb[base0 + (size_t)(lb + j)*D_INNER];
                zb[nxt][j] = xz[zbase0 + (size_t)(lb + j)*(2*D_INNER)];
            }
        }
        #pragma unroll
        for (int j = 0; j < SCH; j++) {
            int l = c * SCH + j;
            float u = ub[cur][j], z = zb[cur][j];
            float dt0 = bdt, dt1 = 0.f;
            #pragma unroll
            for (int r = 0; r < DT_RANK; r += 2) {
                dt0 += sdbl[l][r]   * wdt[r];
                dt1 += sdbl[l][r+1] * wdt[r+1];
            }
            float dt = dt0 + dt1;
            dt = (dt > 15.f) ? dt : __logf(1.f + __expf(dt));
            float du = dt * u;
            float e[8];
            if (structured) {
                float w = __expf(dt * a0);      // w^1
                float w2 = w * w;
                float w4 = w2 * w2;
                e[0] = w;        e[1] = w2;
                e[2] = w2 * w;   e[3] = w4;
                e[4] = w4 * w;   e[5] = w4 * w2;
                e[6] = w4 * e[2]; e[7] = w4 * w4;
                if (half) {
                    float w8 = e[7];
                    #pragma unroll
                    for (int n = 0; n < 8; n++) e[n] *= w8;   // w^(9..16)
                }
            } else {
                #pragma unroll
                for (int n = 0; n < 8; n++) e[n] = __expf(dt * a[n]);
            }
            float yv0 = 0.f, yv1 = 0.f;
            int sb_off = DT_RANK + half*8;
            int sc_off = DT_RANK + D_STATE + half*8;
            #pragma unroll
            for (int n = 0; n < 8; n += 2) {
                h[n]   = e[n]   * h[n]   + du * sdbl[l][sb_off + n];
                h[n+1] = e[n+1] * h[n+1] + du * sdbl[l][sb_off + n+1];
                yv0 += h[n]   * sdbl[l][sc_off + n];
                yv1 += h[n+1] * sdbl[l][sc_off + n+1];
            }
            float yv = yv0 + yv1;
            yv += __shfl_xor_sync(0xffffffffu, yv, 1);
            if (!half) {
                yv += u * Dd;
                float sig = 1.f / (1.f + __expf(-z));
                y[base0 + (size_t)l*D_INNER] = tf32r(yv * (z * sig));
            }
        }
    }
}

// ================= final: LN(residual last token) + head =================
__global__ void final_kernel(const float* __restrict__ residual,
                             const float* __restrict__ nw, const float* __restrict__ nb,
                             const float* __restrict__ hw, const float* __restrict__ hb,
                             float* __restrict__ out) {
    int b = blockIdx.x;
    int t = threadIdx.x;               // 256 threads
    __shared__ float sh[D_MODEL];
    __shared__ float red[8];
    int row = b*L_SEQ + (L_SEQ - 1);
    float v = 0.f;
    if (t < D_MODEL) v = residual[row*D_MODEL + t];
    float s = v;
    #pragma unroll
    for (int o = 16; o > 0; o >>= 1) s += __shfl_xor_sync(0xffffffffu, s, o);
    if ((t & 31) == 0) red[t >> 5] = s;
    __syncthreads();
    float mean = 0.f;
    #pragma unroll
    for (int i = 0; i < 8; i++) mean += red[i];
    mean *= (1.f/192.f);
    __syncthreads();
    float dv = (t < D_MODEL) ? (v - mean) : 0.f;
    s = dv*dv;
    #pragma unroll
    for (int o = 16; o > 0; o >>= 1) s += __shfl_xor_sync(0xffffffffu, s, o);
    if ((t & 31) == 0) red[t >> 5] = s;
    __syncthreads();
    float var = 0.f;
    #pragma unroll
    for (int i = 0; i < 8; i++) var += red[i];
    var *= (1.f/192.f);
    if (t < D_MODEL) sh[t] = dv * rsqrtf(var + 1e-5f) * nw[t] + nb[t];
    __syncthreads();
    for (int o = t; o < N_CLS; o += 256) {
        float acc = hb[o];
        #pragma unroll 4
        for (int k = 0; k < D_MODEL; k++) acc += sh[k] * hw[o*D_MODEL + k];
        out[b*N_CLS + o] = acc;
    }
}

extern "C" void kernel_launch(void* const* d_in, const int* in_sizes, int n_in,
                              void* d_out, int out_size) {
    const float* x        = (const float*)d_in[0];
    const float* patch_w  = (const float*)d_in[1];
    const float* patch_b  = (const float*)d_in[2];
    const float* in_w     = (const float*)d_in[3];
    const float* conv_w   = (const float*)d_in[4];
    const float* conv_b   = (const float*)d_in[5];
    const float* xproj_w  = (const float*)d_in[6];
    const float* dt_w     = (const float*)d_in[7];
    const float* dt_b     = (const float*)d_in[8];
    const float* A_log    = (const float*)d_in[9];
    const float* D_skip   = (const float*)d_in[10];
    const float* out_w    = (const float*)d_in[11];
    const float* norm_w   = (const float*)d_in[12];
    const float* norm_b   = (const float*)d_in[13];
    const float* normf_w  = (const float*)d_in[14];
    const float* normf_b  = (const float*)d_in[15];
    const float* head_w   = (const float*)d_in[16];
    const float* head_b   = (const float*)d_in[17];
    float* out = (float*)d_out;

    float *residual, *hn, *xz, *xb, *xdbl, *y;
    float *wpatch, *win, *wx, *wout;
    cudaGetSymbolAddress((void**)&residual, g_residual);
    cudaGetSymbolAddress((void**)&hn,       g_hn);
    cudaGetSymbolAddress((void**)&xz,       g_xz);
    cudaGetSymbolAddress((void**)&xb,       g_xb);
    cudaGetSymbolAddress((void**)&xdbl,     g_xdbl);
    cudaGetSymbolAddress((void**)&y,        g_y);
    cudaGetSymbolAddress((void**)&wpatch,   g_wpatch);
    cudaGetSymbolAddress((void**)&win,      g_win);
    cudaGetSymbolAddress((void**)&wx,       g_wx);
    cudaGetSymbolAddress((void**)&wout,     g_wout);

    cudaFuncSetAttribute(gemm_mma,  cudaFuncAttributeMaxDynamicSharedMemorySize, 2*STAGE_BYTES);
    cudaFuncSetAttribute(gemm_wide, cudaFuncAttributeMaxDynamicSharedMemorySize, 3*WIDE_STAGE);
    cudaFuncSetAttribute(gemm_mma,  cudaFuncAttributePreferredSharedMemoryCarveout, 100);
    cudaFuncSetAttribute(gemm_wide, cudaFuncAttributePreferredSharedMemoryCarveout, 100);

    // pre-round GEMM weights to tf32
    round_tf32_kernel<<<512, 256>>>(patch_w, wpatch, D_MODEL*K_PATCH);
    round_tf32_kernel<<<2048, 256>>>(in_w,   win,    DEPTH*2*D_INNER*D_MODEL);
    round_tf32_kernel<<<512, 256>>>(xproj_w, wx,     DEPTH*XPROJ_N*D_INNER);
    round_tf32_kernel<<<1024, 256>>>(out_w,  wout,   DEPTH*D_MODEL*D_INNER);

    // patch embed -> residual (plain write)
    im2col_kernel<<<(ROWS*K_PATCH + 255)/256, 256>>>(x, xz);
    gemm_mma<<<dim3(3, ROWS/128), 256, 2*STAGE_BYTES>>>(xz, wpatch, residual,
                                                        ROWS, D_MODEL, K_PATCH, patch_b, 0,
                                                        K_PATCH, 0);

    for (int i = 0; i < DEPTH; i++) {
        ln_kernel<<<ROWS/8, 256>>>(residual, hn,
                                   norm_w + (size_t)i*D_MODEL, norm_b + (size_t)i*D_MODEL);
        gemm_wide<<<dim3(6, ROWS/128), 256, 3*WIDE_STAGE>>>(
            hn, win + (size_t)i*2*D_INNER*D_MODEL, xz, ROWS, 2*D_INNER, D_MODEL);
        conv_silu_kernel<<<dim3(B_SZ, 4), 384>>>(xz, conv_w + (size_t)i*D_INNER*D_CONV,
                                                 conv_b + (size_t)i*D_INNER, xb);
        // x_proj split-K: z=0 -> K[0:192), z=1 -> K[192:384); halves summed in scan
        gemm_mma<<<dim3(1, ROWS/128, 2), 256, 2*STAGE_BYTES>>>(
            xb, wx + (size_t)i*XPROJ_N*D_INNER, xdbl, ROWS, XPROJ_N, D_INNER/2, nullptr, 0,
            D_INNER, (size_t)ROWS*XPROJ_N);
        scan_kernel<<<dim3(D_INNER/128, B_SZ), 256>>>(
            xb, xdbl, xz, A_log + (size_t)i*D_INNER*D_STATE, D_skip + (size_t)i*D_INNER,
            dt_w + (size_t)i*D_INNER*DT_RANK, dt_b + (size_t)i*D_INNER, y);
        gemm_mma<<<dim3(3, ROWS/128), 256, 2*STAGE_BYTES>>>(
            y, wout + (size_t)i*D_MODEL*D_INNER, residual, ROWS, D_MODEL, D_INNER, nullptr, 1,
            D_INNER, 0);
    }

    final_kernel<<<B_SZ, 256>>>(residual, normf_w, normf_b, head_w, head_b, out);
}